// round 3
// baseline (speedup 1.0000x reference)
#include <cuda_runtime.h>
#include <cuda_bf16.h>
#include <math.h>

#define B_   2
#define T_   8192
#define H_   16
#define KD   32
#define VD   64
#define BT_  64
#define NT_  128
#define NCHUNK 4096   // B*H*NT

// ------------------- device scratch (no allocation allowed) ---------------
__device__ float g_P [NCHUNK*KD*KD];            // 16.8 MB
__device__ float g_C [NCHUNK*KD*VD];            // 33.6 MB
__device__ float g_E [NCHUNK*KD];               // 0.5 MB
__device__ float g_W [NCHUNK*BT_*KD];           // 33.6 MB
__device__ float g_U [(size_t)NCHUNK*BT_*VD];   // 67 MB
__device__ float g_QG[NCHUNK*BT_*KD];           // 33.6 MB
__device__ float g_KD[NCHUNK*KD*BT_];           // 33.6 MB (kd transposed [32][64])
__device__ float g_S [(size_t)NCHUNK*KD*VD];    // 33.6 MB (state entering chunk)

// phase-1 smem layout (floats), padded strides against bank conflicts
#define KQS 33
#define KDS 68
#define OFF_G    0
#define OFF_KQ   2048
#define OFF_KDT  (OFF_KQ + 64*KQS)     // 4160
#define OFF_L    (OFF_KDT + 32*KDS)    // 6336
#define OFF_X    (OFF_L + 4096)        // 10432
#define OFF_B    (OFF_X + 64*96)       // 16576
#define OFF_E    (OFF_B + 64)          // 16640
#define P1_FLOATS (OFF_E + 32)         // 16672
#define P1_BYTES  (P1_FLOATS*4)

// phase-3 smem layout
#define P3_S   0        // S [32][64]
#define P3_VN  2048     // u -> v_new [64][64]
#define P3_A   6144     // Aqk [64][65]
#define P3_WQ  10304    // w / qg [64][33]
#define P3_KD  12416    // kd^T [32][68]
#define P3_FLOATS 14592
#define P3_BYTES  (P3_FLOATS*4)

// ===========================================================================
__global__ void __launch_bounds__(256) phase1_kernel(
    const float* __restrict__ q, const float* __restrict__ k,
    const float* __restrict__ v, const float* __restrict__ graw,
    const float* __restrict__ beta, const float* __restrict__ A_log,
    const float* __restrict__ dt_bias)
{
    extern __shared__ float sm[];
    float* sG   = sm + OFF_G;
    float* sKQ  = sm + OFF_KQ;
    float* sKDT = sm + OFF_KDT;
    float* sL   = sm + OFF_L;
    float* sX   = sm + OFF_X;
    float* sB   = sm + OFF_B;
    float* sE   = sm + OFF_E;

    const int cid  = blockIdx.x;
    const int pair = cid >> 7, c = cid & 127;
    const int b    = pair >> 4, h = pair & 15;
    const int t0   = c * BT_;
    const int tid  = threadIdx.x;
    const int warp = tid >> 5, lane = tid & 31;

    const float expA = __expf(A_log[h]);

    // gate g = -exp(A_log)*softplus(g_raw + dt_bias)
    for (int idx = tid; idx < BT_*KD; idx += 256) {
        int i = idx >> 5, kk = idx & 31;
        float x = graw[((size_t)((b*T_ + t0 + i)*H_ + h) << 5) + kk]
                + dt_bias[h*KD + kk];
        float sp = fmaxf(x, 0.f) + log1pf(__expf(-fabsf(x)));
        sG[idx] = -expA * sp;
    }
    for (int i = tid; i < BT_; i += 256)
        sB[i] = beta[(size_t)(b*T_ + t0 + i)*H_ + h];
    __syncthreads();

    // cumsum along time per k-column (clamped for exp safety), e = exp(last)
    if (tid < KD) {
        float run = 0.f;
        #pragma unroll 8
        for (int i = 0; i < BT_; i++) {
            run += sG[i*KD + tid];
            float rc = fmaxf(run, -80.f);
            sG[i*KD + tid] = rc;
        }
        sE[tid] = __expf(fmaxf(run, -80.f));
    }
    __syncthreads();

    // kg = l2norm(k)*exp(gc) ; kd^T = l2norm(k)*exp(-gc)
    for (int r = warp; r < BT_; r += 8) {
        float kv = k[((size_t)((b*T_+t0+r)*H_ + h) << 5) + lane];
        float ss = kv*kv;
        #pragma unroll
        for (int o = 16; o; o >>= 1) ss += __shfl_xor_sync(0xffffffffu, ss, o);
        float kn = kv / fmaxf(sqrtf(ss), 1e-6f);
        float gc = sG[r*KD + lane];
        sKQ [r*KQS + lane] = kn * __expf(gc);
        sKDT[lane*KDS + r] = kn * __expf(-gc);
    }
    __syncthreads();

    // L[i][j] = b[i] * (kg_i . kd_j)
    {
        int i = tid >> 2, j0 = (tid & 3) << 4;
        float acc[16];
        #pragma unroll
        for (int r = 0; r < 16; r++) acc[r] = 0.f;
        for (int kk = 0; kk < KD; kk++) {
            float kg = sKQ[i*KQS + kk];
            const float4* kd4 = (const float4*)(sKDT + kk*KDS + j0);
            #pragma unroll
            for (int m = 0; m < 4; m++) {
                float4 d = kd4[m];
                acc[4*m+0] = fmaf(kg, d.x, acc[4*m+0]);
                acc[4*m+1] = fmaf(kg, d.y, acc[4*m+1]);
                acc[4*m+2] = fmaf(kg, d.z, acc[4*m+2]);
                acc[4*m+3] = fmaf(kg, d.w, acc[4*m+3]);
            }
        }
        float bi = sB[i];
        #pragma unroll
        for (int r = 0; r < 16; r++) sL[i*64 + j0 + r] = bi*acc[r];
    }

    // rhs x = [ b*kg | b*v ]
    for (int idx = tid; idx < BT_*KD; idx += 256) {
        int i = idx >> 5, kk = idx & 31;
        sX[i*96 + kk] = sB[i]*sKQ[i*KQS + kk];
    }
    for (int idx = tid; idx < BT_*VD; idx += 256) {
        int i = idx >> 6, vv = idx & 63;
        sX[i*96 + 32 + vv] = sB[i]*v[((size_t)((b*T_+t0+i)*H_+h) << 6) + vv];
    }
    __syncthreads();

    // unit-lower forward substitution, 96 independent columns
    if (tid < 96) {
        for (int i = 1; i < BT_; i++) {
            const float* Lr = sL + i*64;
            float a0 = sX[i*96 + tid], a1 = 0.f, a2 = 0.f, a3 = 0.f;
            int j = 0;
            for (; j + 4 <= i; j += 4) {
                a0 = fmaf(-Lr[j+0], sX[(j+0)*96 + tid], a0);
                a1 = fmaf(-Lr[j+1], sX[(j+1)*96 + tid], a1);
                a2 = fmaf(-Lr[j+2], sX[(j+2)*96 + tid], a2);
                a3 = fmaf(-Lr[j+3], sX[(j+3)*96 + tid], a3);
            }
            for (; j < i; j++) a0 = fmaf(-Lr[j], sX[j*96 + tid], a0);
            sX[i*96 + tid] = (a0 + a1) + (a2 + a3);
        }
    }
    __syncthreads();
    // w = x[:, :32], u = x[:, 32:96]

    // P[kk][m] = e[kk] * sum_i kd[i][kk] * w[i][m]
    {
        int kk = tid >> 3, m0 = (tid & 7) << 2;
        float acc[4] = {0.f,0.f,0.f,0.f};
        for (int i = 0; i < BT_; i++) {
            float kd = sKDT[kk*KDS + i];
            const float* xr = sX + i*96 + m0;
            #pragma unroll
            for (int r = 0; r < 4; r++) acc[r] = fmaf(kd, xr[r], acc[r]);
        }
        float e = sE[kk];
        float* dst = g_P + (size_t)cid*1024 + kk*32 + m0;
        #pragma unroll
        for (int r = 0; r < 4; r++) dst[r] = e*acc[r];
    }
    // C[kk][vv] = e[kk] * sum_i kd[i][kk] * u[i][vv]
    {
        int kk = tid >> 3, v0 = (tid & 7) << 3;
        float acc[8] = {0.f,0.f,0.f,0.f,0.f,0.f,0.f,0.f};
        for (int i = 0; i < BT_; i++) {
            float kd = sKDT[kk*KDS + i];
            const float* xr = sX + i*96 + 32 + v0;
            #pragma unroll
            for (int r = 0; r < 8; r++) acc[r] = fmaf(kd, xr[r], acc[r]);
        }
        float e = sE[kk];
        float* dst = g_C + (size_t)cid*2048 + kk*64 + v0;
        #pragma unroll
        for (int r = 0; r < 8; r++) dst[r] = e*acc[r];
    }
    if (tid < KD) g_E[cid*KD + tid] = sE[tid];

    // store w, u, kd^T
    for (int idx = tid; idx < BT_*KD; idx += 256)
        g_W[(size_t)cid*2048 + idx] = sX[(idx>>5)*96 + (idx & 31)];
    for (int idx = tid; idx < BT_*VD; idx += 256)
        g_U[(size_t)cid*4096 + idx] = sX[(idx>>6)*96 + 32 + (idx & 63)];
    for (int idx = tid; idx < KD*BT_; idx += 256)
        g_KD[(size_t)cid*2048 + idx] = sKDT[(idx>>6)*KDS + (idx & 63)];
    __syncthreads();

    // qg = l2norm(q)*K^-0.5*exp(gc)
    for (int r = warp; r < BT_; r += 8) {
        float qv = q[((size_t)((b*T_+t0+r)*H_+h) << 5) + lane];
        float ss = qv*qv;
        #pragma unroll
        for (int o = 16; o; o >>= 1) ss += __shfl_xor_sync(0xffffffffu, ss, o);
        float inv = 0.1767766952966369f / fmaxf(sqrtf(ss), 1e-6f);
        sKQ[r*KQS + lane] = qv*inv*__expf(sG[r*KD + lane]);
    }
    __syncthreads();
    for (int idx = tid; idx < BT_*KD; idx += 256)
        g_QG[(size_t)cid*2048 + idx] = sKQ[(idx>>5)*KQS + (idx & 31)];
}

// ===========================================================================
// Phase 2: scan S_{t+1} = diag(e)S - P S + C ; 32 pairs x 4 V-slices
// ===========================================================================
__global__ void __launch_bounds__(256) phase2_kernel()
{
    const int p = blockIdx.x >> 2;
    const int vbase = (blockIdx.x & 3) << 4;
    const int tid = threadIdx.x;

    __shared__ float sP[1024], sC[512], sE[32], sS[512];

    for (int i = tid; i < 512; i += 256) sS[i] = 0.f;

    float rP[4], rC[2], rE = 0.f;
    {   // prefetch t=0
        size_t cid = (size_t)p*128;
        #pragma unroll
        for (int r = 0; r < 4; r++) rP[r] = g_P[cid*1024 + tid + r*256];
        #pragma unroll
        for (int r = 0; r < 2; r++) {
            int i = tid + r*256, kk = i >> 4, vv = i & 15;
            rC[r] = g_C[cid*2048 + kk*64 + vbase + vv];
        }
        if (tid < 32) rE = g_E[cid*32 + tid];
    }

    for (int t = 0; t < 128; t++) {
        const size_t cid = (size_t)p*128 + t;
        // regs -> smem for this step
        #pragma unroll
        for (int r = 0; r < 4; r++) sP[tid + r*256] = rP[r];
        sC[tid] = rC[0]; sC[tid + 256] = rC[1];
        if (tid < 32) sE[tid] = rE;
        __syncthreads();

        // prefetch t+1
        if (t + 1 < 128) {
            size_t cid1 = cid + 1;
            #pragma unroll
            for (int r = 0; r < 4; r++) rP[r] = g_P[cid1*1024 + tid + r*256];
            #pragma unroll
            for (int r = 0; r < 2; r++) {
                int i = tid + r*256, kk = i >> 4, vv = i & 15;
                rC[r] = g_C[cid1*2048 + kk*64 + vbase + vv];
            }
            if (tid < 32) rE = g_E[cid1*32 + tid];
        }

        // store state entering chunk t, compute next
        float nv[2];
        #pragma unroll
        for (int r = 0; r < 2; r++) {
            int idx = tid + r*256, kk = idx >> 4, vv = idx & 15;
            g_S[cid*2048 + kk*64 + vbase + vv] = sS[idx];
            float a0 = fmaf(sE[kk], sS[idx], sC[idx]);
            float a1 = 0.f;
            const float* Pr = sP + kk*32;
            #pragma unroll
            for (int m = 0; m < 32; m += 2) {
                a0 = fmaf(-Pr[m],   sS[(m)*16   + vv], a0);
                a1 = fmaf(-Pr[m+1], sS[(m+1)*16 + vv], a1);
            }
            nv[r] = a0 + a1;
        }
        __syncthreads();
        sS[tid] = nv[0]; sS[tid + 256] = nv[1];
        __syncthreads();
    }
}

// ===========================================================================
// Phase 3: o = qg S + Aqk (u - w S), Aqk recomputed in smem
// ===========================================================================
__global__ void __launch_bounds__(256) phase3_kernel(float* __restrict__ out)
{
    extern __shared__ float sm[];
    float* sS  = sm + P3_S;
    float* sVn = sm + P3_VN;
    float* sA  = sm + P3_A;    // stride 65
    float* sWQ = sm + P3_WQ;   // stride 33
    float* sKD = sm + P3_KD;   // stride 68

    const int cid  = blockIdx.x;
    const int pair = cid >> 7, c = cid & 127;
    const int b    = pair >> 4, h = pair & 15;
    const int t0   = c * BT_;
    const int tid  = threadIdx.x;

    for (int i = tid; i < 2048; i += 256) sS[i] = g_S[(size_t)cid*2048 + i];
    for (int i = tid; i < 4096; i += 256) sVn[i] = g_U[(size_t)cid*4096 + i];
    for (int i = tid; i < 2048; i += 256)
        sWQ[(i>>5)*33 + (i & 31)] = g_W[(size_t)cid*2048 + i];
    for (int i = tid; i < 2048; i += 256)
        sKD[(i>>6)*68 + (i & 63)] = g_KD[(size_t)cid*2048 + i];
    __syncthreads();

    const int i0 = tid >> 2, c0 = (tid & 3) << 4;

    // v_new = u - w @ S (in place)
    {
        float acc[16];
        const float4* U4 = (const float4*)(sVn + i0*64 + c0);
        #pragma unroll
        for (int r = 0; r < 4; r++) {
            float4 u = U4[r];
            acc[4*r+0]=u.x; acc[4*r+1]=u.y; acc[4*r+2]=u.z; acc[4*r+3]=u.w;
        }
        for (int m = 0; m < KD; m++) {
            float w = sWQ[i0*33 + m];
            const float4* S4 = (const float4*)(sS + m*64 + c0);
            #pragma unroll
            for (int r = 0; r < 4; r++) {
                float4 s = S4[r];
                acc[4*r+0] = fmaf(-w, s.x, acc[4*r+0]);
                acc[4*r+1] = fmaf(-w, s.y, acc[4*r+1]);
                acc[4*r+2] = fmaf(-w, s.z, acc[4*r+2]);
                acc[4*r+3] = fmaf(-w, s.w, acc[4*r+3]);
            }
        }
        __syncthreads();   // everyone read old sVn row before overwrite? rows private per thread-group; sync anyway before reuse
        float4* Vo = (float4*)(sVn + i0*64 + c0);
        #pragma unroll
        for (int r = 0; r < 4; r++)
            Vo[r] = make_float4(acc[4*r], acc[4*r+1], acc[4*r+2], acc[4*r+3]);
    }
    __syncthreads();

    // qg -> sWQ
    for (int i = tid; i < 2048; i += 256)
        sWQ[(i>>5)*33 + (i & 31)] = g_QG[(size_t)cid*2048 + i];
    __syncthreads();

    // Aqk[i][j] = qg_i . kd_j  (full; only j<=i read later)
    {
        int j0 = (tid & 3) << 4;
        float acc[16];
        #pragma unroll
        for (int r = 0; r < 16; r++) acc[r] = 0.f;
        for (int kk = 0; kk < KD; kk++) {
            float qg = sWQ[i0*33 + kk];
            const float4* kd4 = (const float4*)(sKD + kk*68 + j0);
            #pragma unroll
            for (int m = 0; m < 4; m++) {
                float4 d = kd4[m];
                acc[4*m+0] = fmaf(qg, d.x, acc[4*m+0]);
                acc[4*m+1] = fmaf(qg, d.y, acc[4*m+1]);
                acc[4*m+2] = fmaf(qg, d.z, acc[4*m+2]);
                acc[4*m+3] = fmaf(qg, d.w, acc[4*m+3]);
            }
        }
        #pragma unroll
        for (int r = 0; r < 16; r++) sA[i0*65 + j0 + r] = acc[r];
    }
    __syncthreads();

    // o = qg @ S + Aqk @ v_new
    {
        float acc[16];
        #pragma unroll
        for (int r = 0; r < 16; r++) acc[r] = 0.f;
        for (int m = 0; m < KD; m++) {
            float qg = sWQ[i0*33 + m];
            const float4* S4 = (const float4*)(sS + m*64 + c0);
            #pragma unroll
            for (int r = 0; r < 4; r++) {
                float4 s = S4[r];
                acc[4*r+0] = fmaf(qg, s.x, acc[4*r+0]);
                acc[4*r+1] = fmaf(qg, s.y, acc[4*r+1]);
                acc[4*r+2] = fmaf(qg, s.z, acc[4*r+2]);
                acc[4*r+3] = fmaf(qg, s.w, acc[4*r+3]);
            }
        }
        for (int j = 0; j <= i0; j++) {
            float a = sA[i0*65 + j];
            const float4* V4 = (const float4*)(sVn + j*64 + c0);
            #pragma unroll
            for (int r = 0; r < 4; r++) {
                float4 vv = V4[r];
                acc[4*r+0] = fmaf(a, vv.x, acc[4*r+0]);
                acc[4*r+1] = fmaf(a, vv.y, acc[4*r+1]);
                acc[4*r+2] = fmaf(a, vv.z, acc[4*r+2]);
                acc[4*r+3] = fmaf(a, vv.w, acc[4*r+3]);
            }
        }
        float4* O4 = (float4*)(out + (((size_t)(b*T_ + t0 + i0)*H_ + h) << 6) + c0);
        #pragma unroll
        for (int r = 0; r < 4; r++)
            O4[r] = make_float4(acc[4*r], acc[4*r+1], acc[4*r+2], acc[4*r+3]);
    }
}

// ===========================================================================
extern "C" void kernel_launch(void* const* d_in, const int* in_sizes, int n_in,
                              void* d_out, int out_size)
{
    const float* q       = (const float*)d_in[0];
    const float* k       = (const float*)d_in[1];
    const float* v       = (const float*)d_in[2];
    const float* graw    = (const float*)d_in[3];
    const float* beta    = (const float*)d_in[4];
    const float* A_log   = (const float*)d_in[5];
    const float* dt_bias = (const float*)d_in[6];
    float* out = (float*)d_out;

    cudaFuncSetAttribute(phase1_kernel,
        cudaFuncAttributeMaxDynamicSharedMemorySize, P1_BYTES);
    cudaFuncSetAttribute(phase3_kernel,
        cudaFuncAttributeMaxDynamicSharedMemorySize, P3_BYTES);

    phase1_kernel<<<NCHUNK, 256, P1_BYTES>>>(q, k, v, graw, beta, A_log, dt_bias);
    phase2_kernel<<<128, 256>>>();
    phase3_kernel<<<NCHUNK, 256, P3_BYTES>>>(out);
}

// round 4
// speedup vs baseline: 1.5573x; 1.5573x over previous
#include <cuda_runtime.h>
#include <cuda_bf16.h>
#include <math.h>

#define B_   2
#define T_   8192
#define H_   16
#define KD   32
#define VD   64
#define BT_  64
#define NT_  128
#define NCHUNK 4096   // B*H*NT

// ------------------- device scratch (no allocation allowed) ---------------
__device__ float g_P [NCHUNK*KD*KD];            // 16.8 MB
__device__ float g_C [NCHUNK*KD*VD];            // 33.6 MB
__device__ float g_E [NCHUNK*KD];               // 0.5 MB
__device__ float g_W [NCHUNK*BT_*KD];           // 33.6 MB
__device__ float g_U [(size_t)NCHUNK*BT_*VD];   // 67 MB
__device__ float g_QG[NCHUNK*BT_*KD];           // 33.6 MB
__device__ float g_KD[NCHUNK*KD*BT_];           // 33.6 MB (kd^T [32][64])
__device__ float g_S [(size_t)NCHUNK*KD*VD];    // 33.6 MB (state entering chunk)

// phase-1 smem layout (floats)
#define KQS 33
#define KDS 68
#define LS  65
#define OFF_G    0
#define OFF_KQ   2048
#define OFF_KDT  (OFF_KQ + 64*KQS)     // 4160
#define OFF_L    (OFF_KDT + 32*KDS)    // 6336
#define OFF_X    (OFF_L + 64*LS)       // 10496
#define OFF_B    (OFF_X + 64*96)       // 16640
#define OFF_E    (OFF_B + 64)          // 16704
#define P1_FLOATS (OFF_E + 32)         // 16736
#define P1_BYTES  (P1_FLOATS*4)        // 66944

// phase-3 smem layout
#define P3_S   0        // S [32][64]
#define P3_VN  2048     // u -> v_new [64][64]
#define P3_A   6144     // Aqk [64][65]
#define P3_WQ  10304    // w / qg [64][33]
#define P3_KD  12416    // kd^T [32][68]
#define P3_FLOATS 14592
#define P3_BYTES  (P3_FLOATS*4)        // 58368

// ===========================================================================
__global__ void __launch_bounds__(256) phase1_kernel(
    const float* __restrict__ q, const float* __restrict__ k,
    const float* __restrict__ v, const float* __restrict__ graw,
    const float* __restrict__ beta, const float* __restrict__ A_log,
    const float* __restrict__ dt_bias)
{
    extern __shared__ float sm[];
    float* sG   = sm + OFF_G;
    float* sKQ  = sm + OFF_KQ;
    float* sKDT = sm + OFF_KDT;
    float* sL   = sm + OFF_L;
    float* sX   = sm + OFF_X;
    float* sB   = sm + OFF_B;
    float* sE   = sm + OFF_E;

    const int cid  = blockIdx.x;
    const int pair = cid >> 7, c = cid & 127;
    const int b    = pair >> 4, h = pair & 15;
    const int t0   = c * BT_;
    const int tid  = threadIdx.x;
    const int warp = tid >> 5, lane = tid & 31;

    const float expA = __expf(A_log[h]);

    // gate g = -exp(A_log)*softplus(g_raw + dt_bias)
    for (int idx = tid; idx < BT_*KD; idx += 256) {
        int i = idx >> 5, kk = idx & 31;
        float x = graw[((size_t)((b*T_ + t0 + i)*H_ + h) << 5) + kk]
                + dt_bias[h*KD + kk];
        float sp = fmaxf(x, 0.f) + log1pf(__expf(-fabsf(x)));
        sG[idx] = -expA * sp;
    }
    for (int i = tid; i < BT_; i += 256)
        sB[i] = beta[(size_t)(b*T_ + t0 + i)*H_ + h];
    __syncthreads();

    // cumsum along time per k-column (clamped), e = exp(last)
    if (tid < KD) {
        float run = 0.f;
        #pragma unroll 8
        for (int i = 0; i < BT_; i++) {
            run += sG[i*KD + tid];
            sG[i*KD + tid] = fmaxf(run, -80.f);
        }
        sE[tid] = __expf(fmaxf(run, -80.f));
    }
    __syncthreads();

    // kg = l2norm(k)*exp(gc) ; kd^T = l2norm(k)*exp(-gc)
    for (int r = warp; r < BT_; r += 8) {
        float kv = k[((size_t)((b*T_+t0+r)*H_ + h) << 5) + lane];
        float ss = kv*kv;
        #pragma unroll
        for (int o = 16; o; o >>= 1) ss += __shfl_xor_sync(0xffffffffu, ss, o);
        float kn = kv / fmaxf(sqrtf(ss), 1e-6f);
        float gc = sG[r*KD + lane];
        sKQ [r*KQS + lane] = kn * __expf(gc);
        sKDT[lane*KDS + r] = kn * __expf(-gc);
    }
    __syncthreads();

    const int ti = tid >> 4, tj = tid & 15;
    const int i0 = ti << 2, j0 = tj << 2;

    // L[i][j] = b[i]*(kg_i . kd_j), 4x4 register tile
    {
        float acc[16];
        #pragma unroll
        for (int r = 0; r < 16; r++) acc[r] = 0.f;
        #pragma unroll 4
        for (int kk = 0; kk < KD; kk++) {
            float a0 = sKQ[(i0+0)*KQS + kk];
            float a1 = sKQ[(i0+1)*KQS + kk];
            float a2 = sKQ[(i0+2)*KQS + kk];
            float a3 = sKQ[(i0+3)*KQS + kk];
            float4 d = *(const float4*)(sKDT + kk*KDS + j0);
            acc[ 0]=fmaf(a0,d.x,acc[ 0]); acc[ 1]=fmaf(a0,d.y,acc[ 1]);
            acc[ 2]=fmaf(a0,d.z,acc[ 2]); acc[ 3]=fmaf(a0,d.w,acc[ 3]);
            acc[ 4]=fmaf(a1,d.x,acc[ 4]); acc[ 5]=fmaf(a1,d.y,acc[ 5]);
            acc[ 6]=fmaf(a1,d.z,acc[ 6]); acc[ 7]=fmaf(a1,d.w,acc[ 7]);
            acc[ 8]=fmaf(a2,d.x,acc[ 8]); acc[ 9]=fmaf(a2,d.y,acc[ 9]);
            acc[10]=fmaf(a2,d.z,acc[10]); acc[11]=fmaf(a2,d.w,acc[11]);
            acc[12]=fmaf(a3,d.x,acc[12]); acc[13]=fmaf(a3,d.y,acc[13]);
            acc[14]=fmaf(a3,d.z,acc[14]); acc[15]=fmaf(a3,d.w,acc[15]);
        }
        #pragma unroll
        for (int r = 0; r < 4; r++) {
            float bi = sB[i0+r];
            #pragma unroll
            for (int cc = 0; cc < 4; cc++)
                sL[(i0+r)*LS + j0 + cc] = bi*acc[r*4+cc];
        }
    }

    // rhs x = [ b*kg | b*v ]
    for (int idx = tid; idx < BT_*KD; idx += 256) {
        int i = idx >> 5, kk = idx & 31;
        sX[i*96 + kk] = sB[i]*sKQ[i*KQS + kk];
    }
    for (int idx = tid; idx < BT_*VD; idx += 256) {
        int i = idx >> 6, vv = idx & 63;
        sX[i*96 + 32 + vv] = sB[i]*v[((size_t)((b*T_+t0+i)*H_+h) << 6) + vv];
    }
    __syncthreads();

    // -------- blocked forward substitution (4 blocks of 16) --------
    #pragma unroll 1
    for (int blk = 0; blk < 4; ++blk) {
        const int r0 = blk << 4;
        if (blk) {
            // rows r0..r0+15: rhs -= L[:, 0..r0) @ x[0..r0)
            const int ur = tid >> 4;          // 0..15
            const int uc = (tid & 15) * 6;    // 0..90
            float acc[6];
            #pragma unroll
            for (int cc = 0; cc < 6; cc++) acc[cc] = sX[(r0+ur)*96 + uc + cc];
            for (int kx = 0; kx < r0; kx++) {
                float a = sL[(r0+ur)*LS + kx];
                #pragma unroll
                for (int cc = 0; cc < 6; cc++)
                    acc[cc] = fmaf(-a, sX[kx*96 + uc + cc], acc[cc]);
            }
            #pragma unroll
            for (int cc = 0; cc < 6; cc++) sX[(r0+ur)*96 + uc + cc] = acc[cc];
            __syncthreads();
        }
        // in-block solve: 96 columns, each private to one thread
        if (tid < 96) {
            #pragma unroll 1
            for (int i = 1; i < 16; i++) {
                const int row = r0 + i;
                const float* Lr = sL + row*LS + r0;
                float a = sX[row*96 + tid];
                for (int j = 0; j < i; j++)
                    a = fmaf(-Lr[j], sX[(r0+j)*96 + tid], a);
                sX[row*96 + tid] = a;
            }
        }
        __syncthreads();
    }
    // w = x[:, :32], u = x[:, 32:96]

    // -------- fused P|C = e * (kd^T @ x)  (32x96, 4x3 tiles) --------
    {
        const int kk0 = (tid >> 5) << 2;      // 0..28
        const int c0  = (tid & 31) * 3;       // 0..93
        float acc[12];
        #pragma unroll
        for (int r = 0; r < 12; r++) acc[r] = 0.f;
        #pragma unroll 4
        for (int i = 0; i < BT_; i++) {
            float d0 = sKDT[(kk0+0)*KDS + i];
            float d1 = sKDT[(kk0+1)*KDS + i];
            float d2 = sKDT[(kk0+2)*KDS + i];
            float d3 = sKDT[(kk0+3)*KDS + i];
            float x0 = sX[i*96 + c0 + 0];
            float x1 = sX[i*96 + c0 + 1];
            float x2 = sX[i*96 + c0 + 2];
            acc[0]=fmaf(d0,x0,acc[0]); acc[ 1]=fmaf(d0,x1,acc[ 1]); acc[ 2]=fmaf(d0,x2,acc[ 2]);
            acc[3]=fmaf(d1,x0,acc[3]); acc[ 4]=fmaf(d1,x1,acc[ 4]); acc[ 5]=fmaf(d1,x2,acc[ 5]);
            acc[6]=fmaf(d2,x0,acc[6]); acc[ 7]=fmaf(d2,x1,acc[ 7]); acc[ 8]=fmaf(d2,x2,acc[ 8]);
            acc[9]=fmaf(d3,x0,acc[9]); acc[10]=fmaf(d3,x1,acc[10]); acc[11]=fmaf(d3,x2,acc[11]);
        }
        #pragma unroll
        for (int r = 0; r < 4; r++) {
            float e = sE[kk0+r];
            #pragma unroll
            for (int cc = 0; cc < 3; cc++) {
                int col = c0 + cc;
                float val = e*acc[r*3+cc];
                if (col < 32) g_P[(size_t)cid*1024 + (kk0+r)*32 + col] = val;
                else          g_C[(size_t)cid*2048 + (kk0+r)*64 + (col-32)] = val;
            }
        }
    }
    if (tid < KD) g_E[cid*KD + tid] = sE[tid];

    // store w, u, kd^T
    for (int idx = tid; idx < BT_*KD; idx += 256)
        g_W[(size_t)cid*2048 + idx] = sX[(idx>>5)*96 + (idx & 31)];
    for (int idx = tid; idx < BT_*VD; idx += 256)
        g_U[(size_t)cid*4096 + idx] = sX[(idx>>6)*96 + 32 + (idx & 63)];
    for (int idx = tid; idx < KD*BT_; idx += 256)
        g_KD[(size_t)cid*2048 + idx] = sKDT[(idx>>6)*KDS + (idx & 63)];
    __syncthreads();

    // qg = l2norm(q)*K^-0.5*exp(gc)
    for (int r = warp; r < BT_; r += 8) {
        float qv = q[((size_t)((b*T_+t0+r)*H_+h) << 5) + lane];
        float ss = qv*qv;
        #pragma unroll
        for (int o = 16; o; o >>= 1) ss += __shfl_xor_sync(0xffffffffu, ss, o);
        float inv = 0.1767766952966369f / fmaxf(sqrtf(ss), 1e-6f);
        sKQ[r*KQS + lane] = qv*inv*__expf(sG[r*KD + lane]);
    }
    __syncthreads();
    for (int idx = tid; idx < BT_*KD; idx += 256)
        g_QG[(size_t)cid*2048 + idx] = sKQ[(idx>>5)*KQS + (idx & 31)];
}

// ===========================================================================
// Phase 2: S_{t+1} = diag(e)S - P S + C.  1 warp per (pair, 8-col slice).
// State lives in registers (lane = kk); cross-lane dot via shfl.
// ===========================================================================
#define P4C(arr, m) ( ((m)&3)==0 ? arr[(m)>>2].x : ((m)&3)==1 ? arr[(m)>>2].y \
                    : ((m)&3)==2 ? arr[(m)>>2].z : arr[(m)>>2].w )

__global__ void __launch_bounds__(32) phase2_kernel()
{
    const int p     = blockIdx.x >> 3;
    const int vbase = (blockIdx.x & 7) << 3;
    const int lane  = threadIdx.x;
    const size_t base = (size_t)p*128;

    float4 Pc[8], Pn[8], Cc[2], Cn[2];
    float  ec, en;
    float  s[8];
    #pragma unroll
    for (int j = 0; j < 8; j++) s[j] = 0.f;

    {
        const float4* Pp = (const float4*)(g_P + base*1024 + lane*32);
        #pragma unroll
        for (int r = 0; r < 8; r++) Pc[r] = Pp[r];
        const float4* Cp = (const float4*)(g_C + base*2048 + lane*64 + vbase);
        Cc[0] = Cp[0]; Cc[1] = Cp[1];
        ec = g_E[base*32 + lane];
    }

    #pragma unroll 1
    for (int t = 0; t < 128; t++) {
        const size_t cid = base + t;
        if (t + 1 < 128) {
            const size_t cid1 = cid + 1;
            const float4* Pp = (const float4*)(g_P + cid1*1024 + lane*32);
            #pragma unroll
            for (int r = 0; r < 8; r++) Pn[r] = Pp[r];
            const float4* Cp = (const float4*)(g_C + cid1*2048 + lane*64 + vbase);
            Cn[0] = Cp[0]; Cn[1] = Cp[1];
            en = g_E[cid1*32 + lane];
        }
        // store state entering chunk t
        float4* Sp = (float4*)(g_S + cid*2048 + lane*64 + vbase);
        Sp[0] = make_float4(s[0], s[1], s[2], s[3]);
        Sp[1] = make_float4(s[4], s[5], s[6], s[7]);

        float acc[8];
        acc[0]=fmaf(ec,s[0],Cc[0].x); acc[1]=fmaf(ec,s[1],Cc[0].y);
        acc[2]=fmaf(ec,s[2],Cc[0].z); acc[3]=fmaf(ec,s[3],Cc[0].w);
        acc[4]=fmaf(ec,s[4],Cc[1].x); acc[5]=fmaf(ec,s[5],Cc[1].y);
        acc[6]=fmaf(ec,s[6],Cc[1].z); acc[7]=fmaf(ec,s[7],Cc[1].w);

        #pragma unroll
        for (int m = 0; m < 32; m++) {
            float pm = P4C(Pc, m);
            #pragma unroll
            for (int j = 0; j < 8; j++)
                acc[j] = fmaf(-pm, __shfl_sync(0xffffffffu, s[j], m), acc[j]);
        }
        #pragma unroll
        for (int j = 0; j < 8; j++) s[j] = acc[j];
        #pragma unroll
        for (int r = 0; r < 8; r++) Pc[r] = Pn[r];
        Cc[0] = Cn[0]; Cc[1] = Cn[1];
        ec = en;
    }
}

// ===========================================================================
// Phase 3: o = qg S + Aqk (u - w S) ; 4x4 register tiles everywhere
// ===========================================================================
__global__ void __launch_bounds__(256) phase3_kernel(float* __restrict__ out)
{
    extern __shared__ float sm[];
    float* sS  = sm + P3_S;
    float* sVn = sm + P3_VN;
    float* sA  = sm + P3_A;    // stride 65
    float* sWQ = sm + P3_WQ;   // stride 33
    float* sKD = sm + P3_KD;   // stride 68

    const int cid  = blockIdx.x;
    const int pair = cid >> 7, c = cid & 127;
    const int b    = pair >> 4, h = pair & 15;
    const int t0   = c * BT_;
    const int tid  = threadIdx.x;

    for (int i = tid; i < 2048; i += 256) sS[i]  = g_S[(size_t)cid*2048 + i];
    for (int i = tid; i < 4096; i += 256) sVn[i] = g_U[(size_t)cid*4096 + i];
    for (int i = tid; i < 2048; i += 256)
        sWQ[(i>>5)*33 + (i & 31)] = g_W[(size_t)cid*2048 + i];
    for (int i = tid; i < 2048; i += 256)
        sKD[(i>>6)*68 + (i & 63)] = g_KD[(size_t)cid*2048 + i];
    __syncthreads();

    const int ti = tid >> 4, tj = tid & 15;
    const int i0 = ti << 2, c0 = tj << 2;

    // ---- v_new = u - w @ S (tile private -> no pre-sync needed) ----
    {
        float acc[16];
        #pragma unroll
        for (int r = 0; r < 4; r++) {
            float4 u = *(const float4*)(sVn + (i0+r)*64 + c0);
            acc[r*4+0]=u.x; acc[r*4+1]=u.y; acc[r*4+2]=u.z; acc[r*4+3]=u.w;
        }
        #pragma unroll 4
        for (int m = 0; m < KD; m++) {
            float w0 = sWQ[(i0+0)*33 + m];
            float w1 = sWQ[(i0+1)*33 + m];
            float w2 = sWQ[(i0+2)*33 + m];
            float w3 = sWQ[(i0+3)*33 + m];
            float4 sv = *(const float4*)(sS + m*64 + c0);
            acc[ 0]=fmaf(-w0,sv.x,acc[ 0]); acc[ 1]=fmaf(-w0,sv.y,acc[ 1]);
            acc[ 2]=fmaf(-w0,sv.z,acc[ 2]); acc[ 3]=fmaf(-w0,sv.w,acc[ 3]);
            acc[ 4]=fmaf(-w1,sv.x,acc[ 4]); acc[ 5]=fmaf(-w1,sv.y,acc[ 5]);
            acc[ 6]=fmaf(-w1,sv.z,acc[ 6]); acc[ 7]=fmaf(-w1,sv.w,acc[ 7]);
            acc[ 8]=fmaf(-w2,sv.x,acc[ 8]); acc[ 9]=fmaf(-w2,sv.y,acc[ 9]);
            acc[10]=fmaf(-w2,sv.z,acc[10]); acc[11]=fmaf(-w2,sv.w,acc[11]);
            acc[12]=fmaf(-w3,sv.x,acc[12]); acc[13]=fmaf(-w3,sv.y,acc[13]);
            acc[14]=fmaf(-w3,sv.z,acc[14]); acc[15]=fmaf(-w3,sv.w,acc[15]);
        }
        #pragma unroll
        for (int r = 0; r < 4; r++)
            *(float4*)(sVn + (i0+r)*64 + c0) =
                make_float4(acc[r*4], acc[r*4+1], acc[r*4+2], acc[r*4+3]);
    }
    __syncthreads();

    // qg -> sWQ (w fully consumed above)
    for (int i = tid; i < 2048; i += 256)
        sWQ[(i>>5)*33 + (i & 31)] = g_QG[(size_t)cid*2048 + i];
    __syncthreads();

    // ---- Aqk[i][j] = qg_i . kd_j (full; masked at use) ----
    {
        float acc[16];
        #pragma unroll
        for (int r = 0; r < 16; r++) acc[r] = 0.f;
        #pragma unroll 4
        for (int kk = 0; kk < KD; kk++) {
            float a0 = sWQ[(i0+0)*33 + kk];
            float a1 = sWQ[(i0+1)*33 + kk];
            float a2 = sWQ[(i0+2)*33 + kk];
            float a3 = sWQ[(i0+3)*33 + kk];
            float4 d = *(const float4*)(sKD + kk*68 + c0);
            acc[ 0]=fmaf(a0,d.x,acc[ 0]); acc[ 1]=fmaf(a0,d.y,acc[ 1]);
            acc[ 2]=fmaf(a0,d.z,acc[ 2]); acc[ 3]=fmaf(a0,d.w,acc[ 3]);
            acc[ 4]=fmaf(a1,d.x,acc[ 4]); acc[ 5]=fmaf(a1,d.y,acc[ 5]);
            acc[ 6]=fmaf(a1,d.z,acc[ 6]); acc[ 7]=fmaf(a1,d.w,acc[ 7]);
            acc[ 8]=fmaf(a2,d.x,acc[ 8]); acc[ 9]=fmaf(a2,d.y,acc[ 9]);
            acc[10]=fmaf(a2,d.z,acc[10]); acc[11]=fmaf(a2,d.w,acc[11]);
            acc[12]=fmaf(a3,d.x,acc[12]); acc[13]=fmaf(a3,d.y,acc[13]);
            acc[14]=fmaf(a3,d.z,acc[14]); acc[15]=fmaf(a3,d.w,acc[15]);
        }
        #pragma unroll
        for (int r = 0; r < 4; r++)
            #pragma unroll
            for (int cc = 0; cc < 4; cc++)
                sA[(i0+r)*65 + c0 + cc] = acc[r*4+cc];
    }
    __syncthreads();

    // ---- o = qg @ S + Aqk @ v_new ----
    {
        float acc[16];
        #pragma unroll
        for (int r = 0; r < 16; r++) acc[r] = 0.f;
        #pragma unroll 4
        for (int m = 0; m < KD; m++) {
            float a0 = sWQ[(i0+0)*33 + m];
            float a1 = sWQ[(i0+1)*33 + m];
            float a2 = sWQ[(i0+2)*33 + m];
            float a3 = sWQ[(i0+3)*33 + m];
            float4 sv = *(const float4*)(sS + m*64 + c0);
            acc[ 0]=fmaf(a0,sv.x,acc[ 0]); acc[ 1]=fmaf(a0,sv.y,acc[ 1]);
            acc[ 2]=fmaf(a0,sv.z,acc[ 2]); acc[ 3]=fmaf(a0,sv.w,acc[ 3]);
            acc[ 4]=fmaf(a1,sv.x,acc[ 4]); acc[ 5]=fmaf(a1,sv.y,acc[ 5]);
            acc[ 6]=fmaf(a1,sv.z,acc[ 6]); acc[ 7]=fmaf(a1,sv.w,acc[ 7]);
            acc[ 8]=fmaf(a2,sv.x,acc[ 8]); acc[ 9]=fmaf(a2,sv.y,acc[ 9]);
            acc[10]=fmaf(a2,sv.z,acc[10]); acc[11]=fmaf(a2,sv.w,acc[11]);
            acc[12]=fmaf(a3,sv.x,acc[12]); acc[13]=fmaf(a3,sv.y,acc[13]);
            acc[14]=fmaf(a3,sv.z,acc[14]); acc[15]=fmaf(a3,sv.w,acc[15]);
        }
        for (int j = 0; j <= i0 + 3; j++) {
            float a0 = (j <= i0+0) ? sA[(i0+0)*65 + j] : 0.f;
            float a1 = (j <= i0+1) ? sA[(i0+1)*65 + j] : 0.f;
            float a2 = (j <= i0+2) ? sA[(i0+2)*65 + j] : 0.f;
            float a3 = (j <= i0+3) ? sA[(i0+3)*65 + j] : 0.f;
            float4 vv = *(const float4*)(sVn + j*64 + c0);
            acc[ 0]=fmaf(a0,vv.x,acc[ 0]); acc[ 1]=fmaf(a0,vv.y,acc[ 1]);
            acc[ 2]=fmaf(a0,vv.z,acc[ 2]); acc[ 3]=fmaf(a0,vv.w,acc[ 3]);
            acc[ 4]=fmaf(a1,vv.x,acc[ 4]); acc[ 5]=fmaf(a1,vv.y,acc[ 5]);
            acc[ 6]=fmaf(a1,vv.z,acc[ 6]); acc[ 7]=fmaf(a1,vv.w,acc[ 7]);
            acc[ 8]=fmaf(a2,vv.x,acc[ 8]); acc[ 9]=fmaf(a2,vv.y,acc[ 9]);
            acc[10]=fmaf(a2,vv.z,acc[10]); acc[11]=fmaf(a2,vv.w,acc[11]);
            acc[12]=fmaf(a3,vv.x,acc[12]); acc[13]=fmaf(a3,vv.y,acc[13]);
            acc[14]=fmaf(a3,vv.z,acc[14]); acc[15]=fmaf(a3,vv.w,acc[15]);
        }
        #pragma unroll
        for (int r = 0; r < 4; r++) {
            float4* O4 = (float4*)(out + (((size_t)(b*T_ + t0 + i0 + r)*H_ + h) << 6) + c0);
            *O4 = make_float4(acc[r*4], acc[r*4+1], acc[r*4+2], acc[r*4+3]);
        }
    }
}

// ===========================================================================
extern "C" void kernel_launch(void* const* d_in, const int* in_sizes, int n_in,
                              void* d_out, int out_size)
{
    const float* q       = (const float*)d_in[0];
    const float* k       = (const float*)d_in[1];
    const float* v       = (const float*)d_in[2];
    const float* graw    = (const float*)d_in[3];
    const float* beta    = (const float*)d_in[4];
    const float* A_log   = (const float*)d_in[5];
    const float* dt_bias = (const float*)d_in[6];
    float* out = (float*)d_out;

    cudaFuncSetAttribute(phase1_kernel,
        cudaFuncAttributeMaxDynamicSharedMemorySize, P1_BYTES);
    cudaFuncSetAttribute(phase3_kernel,
        cudaFuncAttributeMaxDynamicSharedMemorySize, P3_BYTES);

    phase1_kernel<<<NCHUNK, 256, P1_BYTES>>>(q, k, v, graw, beta, A_log, dt_bias);
    phase2_kernel<<<256, 32>>>();
    phase3_kernel<<<NCHUNK, 256, P3_BYTES>>>(out);
}

// round 5
// speedup vs baseline: 1.5585x; 1.0007x over previous
#include <cuda_runtime.h>
#include <cuda_bf16.h>
#include <math.h>

#define B_   2
#define T_   8192
#define H_   16
#define KD   32
#define VD   64
#define BT_  64
#define NT_  128
#define NCHUNK 4096   // B*H*NT

// ------------------- device scratch (no allocation allowed) ---------------
__device__ float g_P [NCHUNK*KD*KD];            // 16.8 MB
__device__ float g_C [NCHUNK*KD*VD];            // 33.6 MB
__device__ float g_E [NCHUNK*KD];               // 0.5 MB
__device__ float g_W [NCHUNK*BT_*KD];           // 33.6 MB
__device__ float g_U [(size_t)NCHUNK*BT_*VD];   // 67 MB
__device__ float g_QG[NCHUNK*BT_*KD];           // 33.6 MB
__device__ float g_KD[NCHUNK*KD*BT_];           // 33.6 MB (kd^T [32][64])
__device__ float g_S [(size_t)NCHUNK*KD*VD];    // 33.6 MB (state entering chunk)

// phase-1 smem layout (floats)
#define KQS 33
#define KDS 68
#define LS  65
#define OFF_G    0
#define OFF_KQ   2048
#define OFF_KDT  (OFF_KQ + 64*KQS)     // 4160
#define OFF_L    (OFF_KDT + 32*KDS)    // 6336
#define OFF_X    (OFF_L + 64*LS)       // 10496
#define OFF_B    (OFF_X + 64*96)       // 16640
#define OFF_E    (OFF_B + 64)          // 16704
#define P1_FLOATS (OFF_E + 32)         // 16736
#define P1_BYTES  (P1_FLOATS*4)        // 66944

// phase-3 smem layout
#define P3_S   0        // S [32][64]
#define P3_VN  2048     // u -> v_new [64][64]
#define P3_A   6144     // Aqk [64][65]
#define P3_WQ  10304    // w / qg [64][33]
#define P3_KD  12416    // kd^T [32][68]
#define P3_FLOATS 14592
#define P3_BYTES  (P3_FLOATS*4)        // 58368

// ===========================================================================
__global__ void __launch_bounds__(256) phase1_kernel(
    const float* __restrict__ q, const float* __restrict__ k,
    const float* __restrict__ v, const float* __restrict__ graw,
    const float* __restrict__ beta, const float* __restrict__ A_log,
    const float* __restrict__ dt_bias)
{
    extern __shared__ float sm[];
    float* sG   = sm + OFF_G;
    float* sKQ  = sm + OFF_KQ;
    float* sKDT = sm + OFF_KDT;
    float* sL   = sm + OFF_L;
    float* sX   = sm + OFF_X;
    float* sB   = sm + OFF_B;
    float* sE   = sm + OFF_E;

    const int cid  = blockIdx.x;
    const int pair = cid >> 7, c = cid & 127;
    const int b    = pair >> 4, h = pair & 15;
    const int t0   = c * BT_;
    const int tid  = threadIdx.x;
    const int warp = tid >> 5, lane = tid & 31;

    const float expA = __expf(A_log[h]);

    // gate g = -exp(A_log)*softplus(g_raw + dt_bias)
    for (int idx = tid; idx < BT_*KD; idx += 256) {
        int i = idx >> 5, kk = idx & 31;
        float x = graw[((size_t)((b*T_ + t0 + i)*H_ + h) << 5) + kk]
                + dt_bias[h*KD + kk];
        float sp = fmaxf(x, 0.f) + log1pf(__expf(-fabsf(x)));
        sG[idx] = -expA * sp;
    }
    for (int i = tid; i < BT_; i += 256)
        sB[i] = beta[(size_t)(b*T_ + t0 + i)*H_ + h];
    __syncthreads();

    // cumsum along time per k-column (clamped), e = exp(last)
    if (tid < KD) {
        float run = 0.f;
        #pragma unroll 8
        for (int i = 0; i < BT_; i++) {
            run += sG[i*KD + tid];
            sG[i*KD + tid] = fmaxf(run, -80.f);
        }
        sE[tid] = __expf(fmaxf(run, -80.f));
    }
    __syncthreads();

    // kg = l2norm(k)*exp(gc) ; kd^T = l2norm(k)*exp(-gc)
    for (int r = warp; r < BT_; r += 8) {
        float kv = k[((size_t)((b*T_+t0+r)*H_ + h) << 5) + lane];
        float ss = kv*kv;
        #pragma unroll
        for (int o = 16; o; o >>= 1) ss += __shfl_xor_sync(0xffffffffu, ss, o);
        float kn = kv / fmaxf(sqrtf(ss), 1e-6f);
        float gc = sG[r*KD + lane];
        sKQ [r*KQS + lane] = kn * __expf(gc);
        sKDT[lane*KDS + r] = kn * __expf(-gc);
    }
    __syncthreads();

    const int ti = tid >> 4, tj = tid & 15;
    const int i0 = ti << 2, j0 = tj << 2;

    // L[i][j] = b[i]*(kg_i . kd_j), 4x4 register tile
    {
        float acc[16];
        #pragma unroll
        for (int r = 0; r < 16; r++) acc[r] = 0.f;
        #pragma unroll 4
        for (int kk = 0; kk < KD; kk++) {
            float a0 = sKQ[(i0+0)*KQS + kk];
            float a1 = sKQ[(i0+1)*KQS + kk];
            float a2 = sKQ[(i0+2)*KQS + kk];
            float a3 = sKQ[(i0+3)*KQS + kk];
            float4 d = *(const float4*)(sKDT + kk*KDS + j0);
            acc[ 0]=fmaf(a0,d.x,acc[ 0]); acc[ 1]=fmaf(a0,d.y,acc[ 1]);
            acc[ 2]=fmaf(a0,d.z,acc[ 2]); acc[ 3]=fmaf(a0,d.w,acc[ 3]);
            acc[ 4]=fmaf(a1,d.x,acc[ 4]); acc[ 5]=fmaf(a1,d.y,acc[ 5]);
            acc[ 6]=fmaf(a1,d.z,acc[ 6]); acc[ 7]=fmaf(a1,d.w,acc[ 7]);
            acc[ 8]=fmaf(a2,d.x,acc[ 8]); acc[ 9]=fmaf(a2,d.y,acc[ 9]);
            acc[10]=fmaf(a2,d.z,acc[10]); acc[11]=fmaf(a2,d.w,acc[11]);
            acc[12]=fmaf(a3,d.x,acc[12]); acc[13]=fmaf(a3,d.y,acc[13]);
            acc[14]=fmaf(a3,d.z,acc[14]); acc[15]=fmaf(a3,d.w,acc[15]);
        }
        #pragma unroll
        for (int r = 0; r < 4; r++) {
            float bi = sB[i0+r];
            #pragma unroll
            for (int cc = 0; cc < 4; cc++)
                sL[(i0+r)*LS + j0 + cc] = bi*acc[r*4+cc];
        }
    }

    // rhs x = [ b*kg | b*v ]
    for (int idx = tid; idx < BT_*KD; idx += 256) {
        int i = idx >> 5, kk = idx & 31;
        sX[i*96 + kk] = sB[i]*sKQ[i*KQS + kk];
    }
    for (int idx = tid; idx < BT_*VD; idx += 256) {
        int i = idx >> 6, vv = idx & 63;
        sX[i*96 + 32 + vv] = sB[i]*v[((size_t)((b*T_+t0+i)*H_+h) << 6) + vv];
    }
    __syncthreads();

    // -------- blocked forward substitution (4 blocks of 16) --------
    #pragma unroll 1
    for (int blk = 0; blk < 4; ++blk) {
        const int r0 = blk << 4;
        if (blk) {
            // rows r0..r0+15: rhs -= L[:, 0..r0) @ x[0..r0)
            const int ur = tid >> 4;          // 0..15
            const int uc = (tid & 15) * 6;    // 0..90
            float acc[6];
            #pragma unroll
            for (int cc = 0; cc < 6; cc++) acc[cc] = sX[(r0+ur)*96 + uc + cc];
            for (int kx = 0; kx < r0; kx++) {
                float a = sL[(r0+ur)*LS + kx];
                #pragma unroll
                for (int cc = 0; cc < 6; cc++)
                    acc[cc] = fmaf(-a, sX[kx*96 + uc + cc], acc[cc]);
            }
            #pragma unroll
            for (int cc = 0; cc < 6; cc++) sX[(r0+ur)*96 + uc + cc] = acc[cc];
            __syncthreads();
        }
        // in-block solve: 96 columns, each private to one thread
        if (tid < 96) {
            #pragma unroll 1
            for (int i = 1; i < 16; i++) {
                const int row = r0 + i;
                const float* Lr = sL + row*LS + r0;
                float a = sX[row*96 + tid];
                for (int j = 0; j < i; j++)
                    a = fmaf(-Lr[j], sX[(r0+j)*96 + tid], a);
                sX[row*96 + tid] = a;
            }
        }
        __syncthreads();
    }
    // w = x[:, :32], u = x[:, 32:96]

    // -------- fused P|C = e * (kd^T @ x)  (32x96, 4x3 tiles) --------
    {
        const int kk0 = (tid >> 5) << 2;      // 0..28
        const int c0  = (tid & 31) * 3;       // 0..93
        float acc[12];
        #pragma unroll
        for (int r = 0; r < 12; r++) acc[r] = 0.f;
        #pragma unroll 4
        for (int i = 0; i < BT_; i++) {
            float d0 = sKDT[(kk0+0)*KDS + i];
            float d1 = sKDT[(kk0+1)*KDS + i];
            float d2 = sKDT[(kk0+2)*KDS + i];
            float d3 = sKDT[(kk0+3)*KDS + i];
            float x0 = sX[i*96 + c0 + 0];
            float x1 = sX[i*96 + c0 + 1];
            float x2 = sX[i*96 + c0 + 2];
            acc[0]=fmaf(d0,x0,acc[0]); acc[ 1]=fmaf(d0,x1,acc[ 1]); acc[ 2]=fmaf(d0,x2,acc[ 2]);
            acc[3]=fmaf(d1,x0,acc[3]); acc[ 4]=fmaf(d1,x1,acc[ 4]); acc[ 5]=fmaf(d1,x2,acc[ 5]);
            acc[6]=fmaf(d2,x0,acc[6]); acc[ 7]=fmaf(d2,x1,acc[ 7]); acc[ 8]=fmaf(d2,x2,acc[ 8]);
            acc[9]=fmaf(d3,x0,acc[9]); acc[10]=fmaf(d3,x1,acc[10]); acc[11]=fmaf(d3,x2,acc[11]);
        }
        #pragma unroll
        for (int r = 0; r < 4; r++) {
            float e = sE[kk0+r];
            #pragma unroll
            for (int cc = 0; cc < 3; cc++) {
                int col = c0 + cc;
                float val = e*acc[r*3+cc];
                if (col < 32) g_P[(size_t)cid*1024 + (kk0+r)*32 + col] = val;
                else          g_C[(size_t)cid*2048 + (kk0+r)*64 + (col-32)] = val;
            }
        }
    }
    if (tid < KD) g_E[cid*KD + tid] = sE[tid];

    // store w, u, kd^T
    for (int idx = tid; idx < BT_*KD; idx += 256)
        g_W[(size_t)cid*2048 + idx] = sX[(idx>>5)*96 + (idx & 31)];
    for (int idx = tid; idx < BT_*VD; idx += 256)
        g_U[(size_t)cid*4096 + idx] = sX[(idx>>6)*96 + 32 + (idx & 63)];
    for (int idx = tid; idx < KD*BT_; idx += 256)
        g_KD[(size_t)cid*2048 + idx] = sKDT[(idx>>6)*KDS + (idx & 63)];
    __syncthreads();

    // qg = l2norm(q)*K^-0.5*exp(gc)
    for (int r = warp; r < BT_; r += 8) {
        float qv = q[((size_t)((b*T_+t0+r)*H_+h) << 5) + lane];
        float ss = qv*qv;
        #pragma unroll
        for (int o = 16; o; o >>= 1) ss += __shfl_xor_sync(0xffffffffu, ss, o);
        float inv = 0.1767766952966369f / fmaxf(sqrtf(ss), 1e-6f);
        sKQ[r*KQS + lane] = qv*inv*__expf(sG[r*KD + lane]);
    }
    __syncthreads();
    for (int idx = tid; idx < BT_*KD; idx += 256)
        g_QG[(size_t)cid*2048 + idx] = sKQ[(idx>>5)*KQS + (idx & 31)];
}

// ===========================================================================
// Phase 2: S_{t+1} = diag(e)S - P S + C.  1 warp per (pair, 8-col slice).
// State lives in registers (lane = kk); cross-lane dot via shfl.
// ===========================================================================
#define P4C(arr, m) ( ((m)&3)==0 ? arr[(m)>>2].x : ((m)&3)==1 ? arr[(m)>>2].y \
                    : ((m)&3)==2 ? arr[(m)>>2].z : arr[(m)>>2].w )

__global__ void __launch_bounds__(32) phase2_kernel()
{
    const int p     = blockIdx.x >> 3;
    const int vbase = (blockIdx.x & 7) << 3;
    const int lane  = threadIdx.x;
    const size_t base = (size_t)p*128;

    float4 Pc[8], Pn[8], Cc[2], Cn[2];
    float  ec, en;
    float  s[8];
    #pragma unroll
    for (int j = 0; j < 8; j++) s[j] = 0.f;

    {
        const float4* Pp = (const float4*)(g_P + base*1024 + lane*32);
        #pragma unroll
        for (int r = 0; r < 8; r++) Pc[r] = Pp[r];
        const float4* Cp = (const float4*)(g_C + base*2048 + lane*64 + vbase);
        Cc[0] = Cp[0]; Cc[1] = Cp[1];
        ec = g_E[base*32 + lane];
    }

    #pragma unroll 1
    for (int t = 0; t < 128; t++) {
        const size_t cid = base + t;
        if (t + 1 < 128) {
            const size_t cid1 = cid + 1;
            const float4* Pp = (const float4*)(g_P + cid1*1024 + lane*32);
            #pragma unroll
            for (int r = 0; r < 8; r++) Pn[r] = Pp[r];
            const float4* Cp = (const float4*)(g_C + cid1*2048 + lane*64 + vbase);
            Cn[0] = Cp[0]; Cn[1] = Cp[1];
            en = g_E[cid1*32 + lane];
        }
        // store state entering chunk t
        float4* Sp = (float4*)(g_S + cid*2048 + lane*64 + vbase);
        Sp[0] = make_float4(s[0], s[1], s[2], s[3]);
        Sp[1] = make_float4(s[4], s[5], s[6], s[7]);

        float acc[8];
        acc[0]=fmaf(ec,s[0],Cc[0].x); acc[1]=fmaf(ec,s[1],Cc[0].y);
        acc[2]=fmaf(ec,s[2],Cc[0].z); acc[3]=fmaf(ec,s[3],Cc[0].w);
        acc[4]=fmaf(ec,s[4],Cc[1].x); acc[5]=fmaf(ec,s[5],Cc[1].y);
        acc[6]=fmaf(ec,s[6],Cc[1].z); acc[7]=fmaf(ec,s[7],Cc[1].w);

        #pragma unroll
        for (int m = 0; m < 32; m++) {
            float pm = P4C(Pc, m);
            #pragma unroll
            for (int j = 0; j < 8; j++)
                acc[j] = fmaf(-pm, __shfl_sync(0xffffffffu, s[j], m), acc[j]);
        }
        #pragma unroll
        for (int j = 0; j < 8; j++) s[j] = acc[j];
        #pragma unroll
        for (int r = 0; r < 8; r++) Pc[r] = Pn[r];
        Cc[0] = Cn[0]; Cc[1] = Cn[1];
        ec = en;
    }
}

// ===========================================================================
// Phase 3: o = qg S + Aqk (u - w S) ; 4x4 register tiles everywhere
// ===========================================================================
__global__ void __launch_bounds__(256) phase3_kernel(float* __restrict__ out)
{
    extern __shared__ float sm[];
    float* sS  = sm + P3_S;
    float* sVn = sm + P3_VN;
    float* sA  = sm + P3_A;    // stride 65
    float* sWQ = sm + P3_WQ;   // stride 33
    float* sKD = sm + P3_KD;   // stride 68

    const int cid  = blockIdx.x;
    const int pair = cid >> 7, c = cid & 127;
    const int b    = pair >> 4, h = pair & 15;
    const int t0   = c * BT_;
    const int tid  = threadIdx.x;

    for (int i = tid; i < 2048; i += 256) sS[i]  = g_S[(size_t)cid*2048 + i];
    for (int i = tid; i < 4096; i += 256) sVn[i] = g_U[(size_t)cid*4096 + i];
    for (int i = tid; i < 2048; i += 256)
        sWQ[(i>>5)*33 + (i & 31)] = g_W[(size_t)cid*2048 + i];
    for (int i = tid; i < 2048; i += 256)
        sKD[(i>>6)*68 + (i & 63)] = g_KD[(size_t)cid*2048 + i];
    __syncthreads();

    const int ti = tid >> 4, tj = tid & 15;
    const int i0 = ti << 2, c0 = tj << 2;

    // ---- v_new = u - w @ S (tile private -> no pre-sync needed) ----
    {
        float acc[16];
        #pragma unroll
        for (int r = 0; r < 4; r++) {
            float4 u = *(const float4*)(sVn + (i0+r)*64 + c0);
            acc[r*4+0]=u.x; acc[r*4+1]=u.y; acc[r*4+2]=u.z; acc[r*4+3]=u.w;
        }
        #pragma unroll 4
        for (int m = 0; m < KD; m++) {
            float w0 = sWQ[(i0+0)*33 + m];
            float w1 = sWQ[(i0+1)*33 + m];
            float w2 = sWQ[(i0+2)*33 + m];
            float w3 = sWQ[(i0+3)*33 + m];
            float4 sv = *(const float4*)(sS + m*64 + c0);
            acc[ 0]=fmaf(-w0,sv.x,acc[ 0]); acc[ 1]=fmaf(-w0,sv.y,acc[ 1]);
            acc[ 2]=fmaf(-w0,sv.z,acc[ 2]); acc[ 3]=fmaf(-w0,sv.w,acc[ 3]);
            acc[ 4]=fmaf(-w1,sv.x,acc[ 4]); acc[ 5]=fmaf(-w1,sv.y,acc[ 5]);
            acc[ 6]=fmaf(-w1,sv.z,acc[ 6]); acc[ 7]=fmaf(-w1,sv.w,acc[ 7]);
            acc[ 8]=fmaf(-w2,sv.x,acc[ 8]); acc[ 9]=fmaf(-w2,sv.y,acc[ 9]);
            acc[10]=fmaf(-w2,sv.z,acc[10]); acc[11]=fmaf(-w2,sv.w,acc[11]);
            acc[12]=fmaf(-w3,sv.x,acc[12]); acc[13]=fmaf(-w3,sv.y,acc[13]);
            acc[14]=fmaf(-w3,sv.z,acc[14]); acc[15]=fmaf(-w3,sv.w,acc[15]);
        }
        #pragma unroll
        for (int r = 0; r < 4; r++)
            *(float4*)(sVn + (i0+r)*64 + c0) =
                make_float4(acc[r*4], acc[r*4+1], acc[r*4+2], acc[r*4+3]);
    }
    __syncthreads();

    // qg -> sWQ (w fully consumed above)
    for (int i = tid; i < 2048; i += 256)
        sWQ[(i>>5)*33 + (i & 31)] = g_QG[(size_t)cid*2048 + i];
    __syncthreads();

    // ---- Aqk[i][j] = qg_i . kd_j (full; masked at use) ----
    {
        float acc[16];
        #pragma unroll
        for (int r = 0; r < 16; r++) acc[r] = 0.f;
        #pragma unroll 4
        for (int kk = 0; kk < KD; kk++) {
            float a0 = sWQ[(i0+0)*33 + kk];
            float a1 = sWQ[(i0+1)*33 + kk];
            float a2 = sWQ[(i0+2)*33 + kk];
            float a3 = sWQ[(i0+3)*33 + kk];
            float4 d = *(const float4*)(sKD + kk*68 + c0);
            acc[ 0]=fmaf(a0,d.x,acc[ 0]); acc[ 1]=fmaf(a0,d.y,acc[ 1]);
            acc[ 2]=fmaf(a0,d.z,acc[ 2]); acc[ 3]=fmaf(a0,d.w,acc[ 3]);
            acc[ 4]=fmaf(a1,d.x,acc[ 4]); acc[ 5]=fmaf(a1,d.y,acc[ 5]);
            acc[ 6]=fmaf(a1,d.z,acc[ 6]); acc[ 7]=fmaf(a1,d.w,acc[ 7]);
            acc[ 8]=fmaf(a2,d.x,acc[ 8]); acc[ 9]=fmaf(a2,d.y,acc[ 9]);
            acc[10]=fmaf(a2,d.z,acc[10]); acc[11]=fmaf(a2,d.w,acc[11]);
            acc[12]=fmaf(a3,d.x,acc[12]); acc[13]=fmaf(a3,d.y,acc[13]);
            acc[14]=fmaf(a3,d.z,acc[14]); acc[15]=fmaf(a3,d.w,acc[15]);
        }
        #pragma unroll
        for (int r = 0; r < 4; r++)
            #pragma unroll
            for (int cc = 0; cc < 4; cc++)
                sA[(i0+r)*65 + c0 + cc] = acc[r*4+cc];
    }
    __syncthreads();

    // ---- o = qg @ S + Aqk @ v_new ----
    {
        float acc[16];
        #pragma unroll
        for (int r = 0; r < 16; r++) acc[r] = 0.f;
        #pragma unroll 4
        for (int m = 0; m < KD; m++) {
            float a0 = sWQ[(i0+0)*33 + m];
            float a1 = sWQ[(i0+1)*33 + m];
            float a2 = sWQ[(i0+2)*33 + m];
            float a3 = sWQ[(i0+3)*33 + m];
            float4 sv = *(const float4*)(sS + m*64 + c0);
            acc[ 0]=fmaf(a0,sv.x,acc[ 0]); acc[ 1]=fmaf(a0,sv.y,acc[ 1]);
            acc[ 2]=fmaf(a0,sv.z,acc[ 2]); acc[ 3]=fmaf(a0,sv.w,acc[ 3]);
            acc[ 4]=fmaf(a1,sv.x,acc[ 4]); acc[ 5]=fmaf(a1,sv.y,acc[ 5]);
            acc[ 6]=fmaf(a1,sv.z,acc[ 6]); acc[ 7]=fmaf(a1,sv.w,acc[ 7]);
            acc[ 8]=fmaf(a2,sv.x,acc[ 8]); acc[ 9]=fmaf(a2,sv.y,acc[ 9]);
            acc[10]=fmaf(a2,sv.z,acc[10]); acc[11]=fmaf(a2,sv.w,acc[11]);
            acc[12]=fmaf(a3,sv.x,acc[12]); acc[13]=fmaf(a3,sv.y,acc[13]);
            acc[14]=fmaf(a3,sv.z,acc[14]); acc[15]=fmaf(a3,sv.w,acc[15]);
        }
        for (int j = 0; j <= i0 + 3; j++) {
            float a0 = (j <= i0+0) ? sA[(i0+0)*65 + j] : 0.f;
            float a1 = (j <= i0+1) ? sA[(i0+1)*65 + j] : 0.f;
            float a2 = (j <= i0+2) ? sA[(i0+2)*65 + j] : 0.f;
            float a3 = (j <= i0+3) ? sA[(i0+3)*65 + j] : 0.f;
            float4 vv = *(const float4*)(sVn + j*64 + c0);
            acc[ 0]=fmaf(a0,vv.x,acc[ 0]); acc[ 1]=fmaf(a0,vv.y,acc[ 1]);
            acc[ 2]=fmaf(a0,vv.z,acc[ 2]); acc[ 3]=fmaf(a0,vv.w,acc[ 3]);
            acc[ 4]=fmaf(a1,vv.x,acc[ 4]); acc[ 5]=fmaf(a1,vv.y,acc[ 5]);
            acc[ 6]=fmaf(a1,vv.z,acc[ 6]); acc[ 7]=fmaf(a1,vv.w,acc[ 7]);
            acc[ 8]=fmaf(a2,vv.x,acc[ 8]); acc[ 9]=fmaf(a2,vv.y,acc[ 9]);
            acc[10]=fmaf(a2,vv.z,acc[10]); acc[11]=fmaf(a2,vv.w,acc[11]);
            acc[12]=fmaf(a3,vv.x,acc[12]); acc[13]=fmaf(a3,vv.y,acc[13]);
            acc[14]=fmaf(a3,vv.z,acc[14]); acc[15]=fmaf(a3,vv.w,acc[15]);
        }
        #pragma unroll
        for (int r = 0; r < 4; r++) {
            float4* O4 = (float4*)(out + (((size_t)(b*T_ + t0 + i0 + r)*H_ + h) << 6) + c0);
            *O4 = make_float4(acc[r*4], acc[r*4+1], acc[r*4+2], acc[r*4+3]);
        }
    }
}

// ===========================================================================
extern "C" void kernel_launch(void* const* d_in, const int* in_sizes, int n_in,
                              void* d_out, int out_size)
{
    const float* q       = (const float*)d_in[0];
    const float* k       = (const float*)d_in[1];
    const float* v       = (const float*)d_in[2];
    const float* graw    = (const float*)d_in[3];
    const float* beta    = (const float*)d_in[4];
    const float* A_log   = (const float*)d_in[5];
    const float* dt_bias = (const float*)d_in[6];
    float* out = (float*)d_out;

    cudaFuncSetAttribute(phase1_kernel,
        cudaFuncAttributeMaxDynamicSharedMemorySize, P1_BYTES);
    cudaFuncSetAttribute(phase3_kernel,
        cudaFuncAttributeMaxDynamicSharedMemorySize, P3_BYTES);

    phase1_kernel<<<NCHUNK, 256, P1_BYTES>>>(q, k, v, graw, beta, A_log, dt_bias);
    phase2_kernel<<<256, 32>>>();
    phase3_kernel<<<NCHUNK, 256, P3_BYTES>>>(out);
}

// round 6
// speedup vs baseline: 2.1688x; 1.3916x over previous
#include <cuda_runtime.h>
#include <cuda_bf16.h>
#include <math.h>

#define B_   2
#define T_   8192
#define H_   16
#define KD   32
#define VD   64
#define BT_  64
#define NT_  128
#define NCHUNK 4096   // B*H*NT

// ------------------- device scratch (no allocation allowed) ---------------
__device__ float g_P [NCHUNK*KD*KD];            // 16.8 MB
__device__ float g_C [NCHUNK*KD*VD];            // 33.6 MB
__device__ float g_E [NCHUNK*KD];               // 0.5 MB
__device__ float g_W [NCHUNK*BT_*KD];           // 33.6 MB
__device__ float g_U [(size_t)NCHUNK*BT_*VD];   // 67 MB
__device__ float g_QG[NCHUNK*BT_*KD];           // 33.6 MB
__device__ float g_KD[NCHUNK*KD*BT_];           // 33.6 MB (kd^T [32][64])
__device__ float g_S [(size_t)NCHUNK*KD*VD];    // 33.6 MB (state entering chunk)

// ---------------- phase-1 smem layout (floats) ----------------
#define P1_KQ   0                    // kg*b rows [64][33]
#define P1_KDT  2112                 // kd^T [32][68]
#define P1_V    4288                 // b*v [64][64]; gcum overlays first 2048
#define P1_L    8384                 // L [64][65]
#define P1_B    12544                // beta [64]
#define P1_E    12608                // e [32]
#define P1_FLOATS 12640
#define P1_BYTES  (P1_FLOATS*4)      // 50560

// ---------------- phase-3 smem layout (floats) ----------------
#define P3_A    0                    // Aqk [64][65]
#define P3_KD2  4160                 // kd^T [32][68]; later S [32][64]
#define P3_WQ   6336                 // qg then w [64][33]
#define P3_VN   8448                 // u -> v_new [64][64]
#define P3_FLOATS 12544
#define P3_BYTES  (P3_FLOATS*4)      // 50176

// ===========================================================================
__global__ void __launch_bounds__(256, 4) phase1_kernel(
    const float* __restrict__ q, const float* __restrict__ k,
    const float* __restrict__ v, const float* __restrict__ graw,
    const float* __restrict__ beta, const float* __restrict__ A_log,
    const float* __restrict__ dt_bias)
{
    extern __shared__ float sm[];
    float* sKQ  = sm + P1_KQ;    // stride 33
    float* sKDT = sm + P1_KDT;   // stride 68
    float* sV   = sm + P1_V;     // stride 64
    float* sG   = sm + P1_V;     // overlay: [64][32] until v load
    float* sL   = sm + P1_L;     // stride 65
    float* sB   = sm + P1_B;
    float* sE   = sm + P1_E;

    const int cid  = blockIdx.x;
    const int pair = cid >> 7, c = cid & 127;
    const int b    = pair >> 4, h = pair & 15;
    const int t0   = c * BT_;
    const int tid  = threadIdx.x;
    const int warp = tid >> 5, lane = tid & 31;

    const float expA = __expf(A_log[h]);

    // ---- gate g = -exp(A_log)*softplus(g_raw + dt_bias), float4 ----
    for (int idx = tid; idx < 512; idx += 256) {
        int i = idx >> 3, q4 = (idx & 7) << 2;
        float4 gr = *(const float4*)(graw + (((size_t)(b*T_ + t0 + i)*H_ + h) << 5) + q4);
        float4 db = *(const float4*)(dt_bias + h*KD + q4);
        float4 o;
        o.x = -expA*(fmaxf(gr.x+db.x,0.f) + log1pf(__expf(-fabsf(gr.x+db.x))));
        o.y = -expA*(fmaxf(gr.y+db.y,0.f) + log1pf(__expf(-fabsf(gr.y+db.y))));
        o.z = -expA*(fmaxf(gr.z+db.z,0.f) + log1pf(__expf(-fabsf(gr.z+db.z))));
        o.w = -expA*(fmaxf(gr.w+db.w,0.f) + log1pf(__expf(-fabsf(gr.w+db.w))));
        *(float4*)(sG + i*KD + q4) = o;
    }
    for (int i = tid; i < BT_; i += 256)
        sB[i] = beta[(size_t)(b*T_ + t0 + i)*H_ + h];
    __syncthreads();

    // ---- cumsum per k-column, e = exp(last) ----
    if (tid < KD) {
        float run = 0.f;
        #pragma unroll 8
        for (int i = 0; i < BT_; i++) {
            run += sG[i*KD + tid];
            sG[i*KD + tid] = fmaxf(run, -80.f);
        }
        sE[tid] = __expf(fmaxf(run, -80.f));
    }
    __syncthreads();

    // ---- k, q rows: kg*b -> sKQ, kd -> sKDT, qg -> g_QG ----
    for (int r = warp; r < BT_; r += 8) {
        float gc = sG[r*KD + lane];
        float eg = __expf(gc);

        float kv = k[((size_t)((b*T_+t0+r)*H_ + h) << 5) + lane];
        float ss = kv*kv;
        #pragma unroll
        for (int o = 16; o; o >>= 1) ss += __shfl_xor_sync(0xffffffffu, ss, o);
        float kn = kv / fmaxf(sqrtf(ss), 1e-6f);
        sKQ [r*33  + lane] = sB[r] * kn * eg;
        sKDT[lane*68 + r]  = kn * __expf(-gc);

        float qv = q[((size_t)((b*T_+t0+r)*H_+h) << 5) + lane];
        float qs = qv*qv;
        #pragma unroll
        for (int o = 16; o; o >>= 1) qs += __shfl_xor_sync(0xffffffffu, qs, o);
        float qn = 0.1767766952966369f * qv / fmaxf(sqrtf(qs), 1e-6f);
        g_QG[(size_t)cid*2048 + r*KD + lane] = qn * eg;
    }
    __syncthreads();   // sG dead from here

    // ---- v*b -> sV (overwrites sG region) ----
    for (int idx = tid; idx < 1024; idx += 256) {
        int i = idx >> 4, c4 = (idx & 15) << 2;
        float4 vv = *(const float4*)(v + (((size_t)(b*T_+t0+i)*H_+h) << 6) + c4);
        float bi = sB[i];
        vv.x *= bi; vv.y *= bi; vv.z *= bi; vv.w *= bi;
        *(float4*)(sV + i*64 + c4) = vv;
    }

    // ---- L[i][j] = (b*kg)_i . kd_j, 4x4 tiles ----
    {
        const int i0 = (tid >> 4) << 2, j0 = (tid & 15) << 2;
        float acc[16];
        #pragma unroll
        for (int r = 0; r < 16; r++) acc[r] = 0.f;
        #pragma unroll 4
        for (int kk = 0; kk < KD; kk++) {
            float a0 = sKQ[(i0+0)*33 + kk];
            float a1 = sKQ[(i0+1)*33 + kk];
            float a2 = sKQ[(i0+2)*33 + kk];
            float a3 = sKQ[(i0+3)*33 + kk];
            float4 d = *(const float4*)(sKDT + kk*68 + j0);
            acc[ 0]=fmaf(a0,d.x,acc[ 0]); acc[ 1]=fmaf(a0,d.y,acc[ 1]);
            acc[ 2]=fmaf(a0,d.z,acc[ 2]); acc[ 3]=fmaf(a0,d.w,acc[ 3]);
            acc[ 4]=fmaf(a1,d.x,acc[ 4]); acc[ 5]=fmaf(a1,d.y,acc[ 5]);
            acc[ 6]=fmaf(a1,d.z,acc[ 6]); acc[ 7]=fmaf(a1,d.w,acc[ 7]);
            acc[ 8]=fmaf(a2,d.x,acc[ 8]); acc[ 9]=fmaf(a2,d.y,acc[ 9]);
            acc[10]=fmaf(a2,d.z,acc[10]); acc[11]=fmaf(a2,d.w,acc[11]);
            acc[12]=fmaf(a3,d.x,acc[12]); acc[13]=fmaf(a3,d.y,acc[13]);
            acc[14]=fmaf(a3,d.z,acc[14]); acc[15]=fmaf(a3,d.w,acc[15]);
        }
        #pragma unroll
        for (int r = 0; r < 4; r++)
            #pragma unroll
            for (int cc = 0; cc < 4; cc++)
                sL[(i0+r)*65 + j0 + cc] = acc[r*4+cc];
    }
    __syncthreads();

    // ---- blocked forward substitution on x = [sKQ | sV] ----
    #pragma unroll 1
    for (int blk = 0; blk < 4; ++blk) {
        const int r0 = blk << 4;
        if (blk) {
            const int ur = tid >> 4, g = tid & 15;
            const int cw = g << 1, cv = g << 2;
            float aw0 = sKQ[(r0+ur)*33 + cw];
            float aw1 = sKQ[(r0+ur)*33 + cw + 1];
            float4 av = *(const float4*)(sV + (r0+ur)*64 + cv);
            const float* Lr = sL + (r0+ur)*65;
            #pragma unroll 4
            for (int kx = 0; kx < r0; kx++) {
                float a = Lr[kx];
                aw0 = fmaf(-a, sKQ[kx*33 + cw],     aw0);
                aw1 = fmaf(-a, sKQ[kx*33 + cw + 1], aw1);
                float4 xv = *(const float4*)(sV + kx*64 + cv);
                av.x = fmaf(-a, xv.x, av.x); av.y = fmaf(-a, xv.y, av.y);
                av.z = fmaf(-a, xv.z, av.z); av.w = fmaf(-a, xv.w, av.w);
            }
            sKQ[(r0+ur)*33 + cw]     = aw0;
            sKQ[(r0+ur)*33 + cw + 1] = aw1;
            *(float4*)(sV + (r0+ur)*64 + cv) = av;
            __syncthreads();
        }
        // in-block solve, columns in registers
        if (tid < 96) {
            float xr[16];
            if (tid < 32) {
                #pragma unroll
                for (int i = 0; i < 16; i++) xr[i] = sKQ[(r0+i)*33 + tid];
            } else {
                const int cc = tid - 32;
                #pragma unroll
                for (int i = 0; i < 16; i++) xr[i] = sV[(r0+i)*64 + cc];
            }
            #pragma unroll
            for (int i = 1; i < 16; i++) {
                const float* Lr = sL + (r0+i)*65 + r0;
                #pragma unroll
                for (int j = 0; j < i; j++)
                    xr[i] = fmaf(-Lr[j], xr[j], xr[i]);
            }
            if (tid < 32) {
                #pragma unroll
                for (int i = 1; i < 16; i++) sKQ[(r0+i)*33 + tid] = xr[i];
            } else {
                const int cc = tid - 32;
                #pragma unroll
                for (int i = 1; i < 16; i++) sV[(r0+i)*64 + cc] = xr[i];
            }
        }
        __syncthreads();
    }
    // w in sKQ, u in sV

    // ---- P = e*(kd^T @ w) ----
    {
        const int kk = tid >> 3, m0 = (tid & 7) << 2;
        float acc[4] = {0.f,0.f,0.f,0.f};
        #pragma unroll 4
        for (int i = 0; i < BT_; i++) {
            float d = sKDT[kk*68 + i];
            acc[0] = fmaf(d, sKQ[i*33 + m0+0], acc[0]);
            acc[1] = fmaf(d, sKQ[i*33 + m0+1], acc[1]);
            acc[2] = fmaf(d, sKQ[i*33 + m0+2], acc[2]);
            acc[3] = fmaf(d, sKQ[i*33 + m0+3], acc[3]);
        }
        float e = sE[kk];
        *(float4*)(g_P + (size_t)cid*1024 + kk*32 + m0) =
            make_float4(e*acc[0], e*acc[1], e*acc[2], e*acc[3]);
    }
    // ---- C = e*(kd^T @ u) ----
    {
        const int kk = tid >> 3, v0 = (tid & 7) << 3;
        float acc[8] = {0.f,0.f,0.f,0.f,0.f,0.f,0.f,0.f};
        #pragma unroll 4
        for (int i = 0; i < BT_; i++) {
            float d = sKDT[kk*68 + i];
            float4 x0 = *(const float4*)(sV + i*64 + v0);
            float4 x1 = *(const float4*)(sV + i*64 + v0 + 4);
            acc[0]=fmaf(d,x0.x,acc[0]); acc[1]=fmaf(d,x0.y,acc[1]);
            acc[2]=fmaf(d,x0.z,acc[2]); acc[3]=fmaf(d,x0.w,acc[3]);
            acc[4]=fmaf(d,x1.x,acc[4]); acc[5]=fmaf(d,x1.y,acc[5]);
            acc[6]=fmaf(d,x1.z,acc[6]); acc[7]=fmaf(d,x1.w,acc[7]);
        }
        float e = sE[kk];
        float* dst = g_C + (size_t)cid*2048 + kk*64 + v0;
        *(float4*)(dst)   = make_float4(e*acc[0], e*acc[1], e*acc[2], e*acc[3]);
        *(float4*)(dst+4) = make_float4(e*acc[4], e*acc[5], e*acc[6], e*acc[7]);
    }
    if (tid < KD) g_E[cid*KD + tid] = sE[tid];

    // ---- store w (scalar lds, coalesced stg), u & kd^T (float4) ----
    for (int idx = tid; idx < 2048; idx += 256)
        g_W[(size_t)cid*2048 + idx] = sKQ[(idx >> 5)*33 + (idx & 31)];
    for (int idx = tid; idx < 1024; idx += 256) {
        int i = idx >> 4, c4 = (idx & 15) << 2;
        *(float4*)(g_U + (size_t)cid*4096 + i*64 + c4) =
            *(const float4*)(sV + i*64 + c4);
    }
    for (int idx = tid; idx < 512; idx += 256) {
        int kk = idx >> 4, c4 = (idx & 15) << 2;
        *(float4*)(g_KD + (size_t)cid*2048 + kk*64 + c4) =
            *(const float4*)(sKDT + kk*68 + c4);
    }
}

// ===========================================================================
// Phase 2: S_{t+1} = diag(e)S - P S + C.  1 warp per (pair, 8-col slice).
// ===========================================================================
#define P4C(arr, m) ( ((m)&3)==0 ? arr[(m)>>2].x : ((m)&3)==1 ? arr[(m)>>2].y \
                    : ((m)&3)==2 ? arr[(m)>>2].z : arr[(m)>>2].w )

__global__ void __launch_bounds__(32) phase2_kernel()
{
    const int p     = blockIdx.x >> 3;
    const int vbase = (blockIdx.x & 7) << 3;
    const int lane  = threadIdx.x;
    const size_t base = (size_t)p*128;

    float4 Pc[8], Pn[8], Cc[2], Cn[2];
    float  ec, en;
    float  s[8];
    #pragma unroll
    for (int j = 0; j < 8; j++) s[j] = 0.f;

    {
        const float4* Pp = (const float4*)(g_P + base*1024 + lane*32);
        #pragma unroll
        for (int r = 0; r < 8; r++) Pc[r] = Pp[r];
        const float4* Cp = (const float4*)(g_C + base*2048 + lane*64 + vbase);
        Cc[0] = Cp[0]; Cc[1] = Cp[1];
        ec = g_E[base*32 + lane];
    }

    #pragma unroll 1
    for (int t = 0; t < 128; t++) {
        const size_t cid = base + t;
        if (t + 1 < 128) {
            const size_t cid1 = cid + 1;
            const float4* Pp = (const float4*)(g_P + cid1*1024 + lane*32);
            #pragma unroll
            for (int r = 0; r < 8; r++) Pn[r] = Pp[r];
            const float4* Cp = (const float4*)(g_C + cid1*2048 + lane*64 + vbase);
            Cn[0] = Cp[0]; Cn[1] = Cp[1];
            en = g_E[cid1*32 + lane];
        }
        float4* Sp = (float4*)(g_S + cid*2048 + lane*64 + vbase);
        Sp[0] = make_float4(s[0], s[1], s[2], s[3]);
        Sp[1] = make_float4(s[4], s[5], s[6], s[7]);

        float acc[8];
        acc[0]=fmaf(ec,s[0],Cc[0].x); acc[1]=fmaf(ec,s[1],Cc[0].y);
        acc[2]=fmaf(ec,s[2],Cc[0].z); acc[3]=fmaf(ec,s[3],Cc[0].w);
        acc[4]=fmaf(ec,s[4],Cc[1].x); acc[5]=fmaf(ec,s[5],Cc[1].y);
        acc[6]=fmaf(ec,s[6],Cc[1].z); acc[7]=fmaf(ec,s[7],Cc[1].w);

        #pragma unroll
        for (int m = 0; m < 32; m++) {
            float pm = P4C(Pc, m);
            #pragma unroll
            for (int j = 0; j < 8; j++)
                acc[j] = fmaf(-pm, __shfl_sync(0xffffffffu, s[j], m), acc[j]);
        }
        #pragma unroll
        for (int j = 0; j < 8; j++) s[j] = acc[j];
        #pragma unroll
        for (int r = 0; r < 8; r++) Pc[r] = Pn[r];
        Cc[0] = Cn[0]; Cc[1] = Cn[1];
        ec = en;
    }
}

// ===========================================================================
// Phase 3: o = qg S + Aqk (u - w S)
// ===========================================================================
__global__ void __launch_bounds__(256, 4) phase3_kernel(float* __restrict__ out)
{
    extern __shared__ float sm[];
    float* sA  = sm + P3_A;     // stride 65
    float* sKD = sm + P3_KD2;   // stride 68; later sS stride 64
    float* sS  = sm + P3_KD2;
    float* sWQ = sm + P3_WQ;    // stride 33
    float* sVn = sm + P3_VN;    // stride 64

    const int cid  = blockIdx.x;
    const int pair = cid >> 7, c = cid & 127;
    const int b    = pair >> 4, h = pair & 15;
    const int t0   = c * BT_;
    const int tid  = threadIdx.x;

    const int i0 = (tid >> 4) << 2, c0 = (tid & 15) << 2;

    // ---- load qg, kd, u ----
    for (int idx = tid; idx < 512; idx += 256) {
        int i = idx >> 3, c4 = (idx & 7) << 2;
        float4 vv = *(const float4*)(g_QG + (size_t)cid*2048 + i*32 + c4);
        sWQ[i*33 + c4+0] = vv.x; sWQ[i*33 + c4+1] = vv.y;
        sWQ[i*33 + c4+2] = vv.z; sWQ[i*33 + c4+3] = vv.w;
    }
    for (int idx = tid; idx < 512; idx += 256) {
        int kk = idx >> 4, c4 = (idx & 15) << 2;
        *(float4*)(sKD + kk*68 + c4) =
            *(const float4*)(g_KD + (size_t)cid*2048 + kk*64 + c4);
    }
    for (int idx = tid; idx < 1024; idx += 256) {
        int i = idx >> 4, c4 = (idx & 15) << 2;
        *(float4*)(sVn + i*64 + c4) =
            *(const float4*)(g_U + (size_t)cid*4096 + i*64 + c4);
    }
    __syncthreads();

    // ---- Aqk = qg . kd^T (full; masked at use) ----
    {
        float acc[16];
        #pragma unroll
        for (int r = 0; r < 16; r++) acc[r] = 0.f;
        #pragma unroll 4
        for (int kk = 0; kk < KD; kk++) {
            float a0 = sWQ[(i0+0)*33 + kk];
            float a1 = sWQ[(i0+1)*33 + kk];
            float a2 = sWQ[(i0+2)*33 + kk];
            float a3 = sWQ[(i0+3)*33 + kk];
            float4 d = *(const float4*)(sKD + kk*68 + c0);
            acc[ 0]=fmaf(a0,d.x,acc[ 0]); acc[ 1]=fmaf(a0,d.y,acc[ 1]);
            acc[ 2]=fmaf(a0,d.z,acc[ 2]); acc[ 3]=fmaf(a0,d.w,acc[ 3]);
            acc[ 4]=fmaf(a1,d.x,acc[ 4]); acc[ 5]=fmaf(a1,d.y,acc[ 5]);
            acc[ 6]=fmaf(a1,d.z,acc[ 6]); acc[ 7]=fmaf(a1,d.w,acc[ 7]);
            acc[ 8]=fmaf(a2,d.x,acc[ 8]); acc[ 9]=fmaf(a2,d.y,acc[ 9]);
            acc[10]=fmaf(a2,d.z,acc[10]); acc[11]=fmaf(a2,d.w,acc[11]);
            acc[12]=fmaf(a3,d.x,acc[12]); acc[13]=fmaf(a3,d.y,acc[13]);
            acc[14]=fmaf(a3,d.z,acc[14]); acc[15]=fmaf(a3,d.w,acc[15]);
        }
        #pragma unroll
        for (int r = 0; r < 4; r++)
            #pragma unroll
            for (int cc = 0; cc < 4; cc++)
                sA[(i0+r)*65 + c0 + cc] = acc[r*4+cc];
    }
    __syncthreads();   // sKD dead

    // ---- load S over sKD region ----
    for (int idx = tid; idx < 512; idx += 256) {
        int kk = idx >> 4, c4 = (idx & 15) << 2;
        *(float4*)(sS + kk*64 + c4) =
            *(const float4*)(g_S + (size_t)cid*2048 + kk*64 + c4);
    }
    __syncthreads();

    // ---- o_acc = qg @ S (qg still resident) ----
    float oacc[16];
    #pragma unroll
    for (int r = 0; r < 16; r++) oacc[r] = 0.f;
    #pragma unroll 4
    for (int m = 0; m < KD; m++) {
        float a0 = sWQ[(i0+0)*33 + m];
        float a1 = sWQ[(i0+1)*33 + m];
        float a2 = sWQ[(i0+2)*33 + m];
        float a3 = sWQ[(i0+3)*33 + m];
        float4 sv = *(const float4*)(sS + m*64 + c0);
        oacc[ 0]=fmaf(a0,sv.x,oacc[ 0]); oacc[ 1]=fmaf(a0,sv.y,oacc[ 1]);
        oacc[ 2]=fmaf(a0,sv.z,oacc[ 2]); oacc[ 3]=fmaf(a0,sv.w,oacc[ 3]);
        oacc[ 4]=fmaf(a1,sv.x,oacc[ 4]); oacc[ 5]=fmaf(a1,sv.y,oacc[ 5]);
        oacc[ 6]=fmaf(a1,sv.z,oacc[ 6]); oacc[ 7]=fmaf(a1,sv.w,oacc[ 7]);
        oacc[ 8]=fmaf(a2,sv.x,oacc[ 8]); oacc[ 9]=fmaf(a2,sv.y,oacc[ 9]);
        oacc[10]=fmaf(a2,sv.z,oacc[10]); oacc[11]=fmaf(a2,sv.w,oacc[11]);
        oacc[12]=fmaf(a3,sv.x,oacc[12]); oacc[13]=fmaf(a3,sv.y,oacc[13]);
        oacc[14]=fmaf(a3,sv.z,oacc[14]); oacc[15]=fmaf(a3,sv.w,oacc[15]);
    }
    __syncthreads();   // qg reads done

    // ---- load w over qg ----
    for (int idx = tid; idx < 512; idx += 256) {
        int i = idx >> 3, c4 = (idx & 7) << 2;
        float4 vv = *(const float4*)(g_W + (size_t)cid*2048 + i*32 + c4);
        sWQ[i*33 + c4+0] = vv.x; sWQ[i*33 + c4+1] = vv.y;
        sWQ[i*33 + c4+2] = vv.z; sWQ[i*33 + c4+3] = vv.w;
    }
    __syncthreads();

    // ---- v_new = u - w @ S (tiles private, in place) ----
    {
        float acc[16];
        #pragma unroll
        for (int r = 0; r < 4; r++) {
            float4 u = *(const float4*)(sVn + (i0+r)*64 + c0);
            acc[r*4+0]=u.x; acc[r*4+1]=u.y; acc[r*4+2]=u.z; acc[r*4+3]=u.w;
        }
        #pragma unroll 4
        for (int m = 0; m < KD; m++) {
            float w0 = sWQ[(i0+0)*33 + m];
            float w1 = sWQ[(i0+1)*33 + m];
            float w2 = sWQ[(i0+2)*33 + m];
            float w3 = sWQ[(i0+3)*33 + m];
            float4 sv = *(const float4*)(sS + m*64 + c0);
            acc[ 0]=fmaf(-w0,sv.x,acc[ 0]); acc[ 1]=fmaf(-w0,sv.y,acc[ 1]);
            acc[ 2]=fmaf(-w0,sv.z,acc[ 2]); acc[ 3]=fmaf(-w0,sv.w,acc[ 3]);
            acc[ 4]=fmaf(-w1,sv.x,acc[ 4]); acc[ 5]=fmaf(-w1,sv.y,acc[ 5]);
            acc[ 6]=fmaf(-w1,sv.z,acc[ 6]); acc[ 7]=fmaf(-w1,sv.w,acc[ 7]);
            acc[ 8]=fmaf(-w2,sv.x,acc[ 8]); acc[ 9]=fmaf(-w2,sv.y,acc[ 9]);
            acc[10]=fmaf(-w2,sv.z,acc[10]); acc[11]=fmaf(-w2,sv.w,acc[11]);
            acc[12]=fmaf(-w3,sv.x,acc[12]); acc[13]=fmaf(-w3,sv.y,acc[13]);
            acc[14]=fmaf(-w3,sv.z,acc[14]); acc[15]=fmaf(-w3,sv.w,acc[15]);
        }
        #pragma unroll
        for (int r = 0; r < 4; r++)
            *(float4*)(sVn + (i0+r)*64 + c0) =
                make_float4(acc[r*4], acc[r*4+1], acc[r*4+2], acc[r*4+3]);
    }
    __syncthreads();

    // ---- o += Aqk @ v_new (masked), store ----
    for (int j = 0; j <= i0 + 3; j++) {
        float a0 = (j <= i0+0) ? sA[(i0+0)*65 + j] : 0.f;
        float a1 = (j <= i0+1) ? sA[(i0+1)*65 + j] : 0.f;
        float a2 = (j <= i0+2) ? sA[(i0+2)*65 + j] : 0.f;
        float a3 = (j <= i0+3) ? sA[(i0+3)*65 + j] : 0.f;
        float4 vv = *(const float4*)(sVn + j*64 + c0);
        oacc[ 0]=fmaf(a0,vv.x,oacc[ 0]); oacc[ 1]=fmaf(a0,vv.y,oacc[ 1]);
        oacc[ 2]=fmaf(a0,vv.z,oacc[ 2]); oacc[ 3]=fmaf(a0,vv.w,oacc[ 3]);
        oacc[ 4]=fmaf(a1,vv.x,oacc[ 4]); oacc[ 5]=fmaf(a1,vv.y,oacc[ 5]);
        oacc[ 6]=fmaf(a1,vv.z,oacc[ 6]); oacc[ 7]=fmaf(a1,vv.w,oacc[ 7]);
        oacc[ 8]=fmaf(a2,vv.x,oacc[ 8]); oacc[ 9]=fmaf(a2,vv.y,oacc[ 9]);
        oacc[10]=fmaf(a2,vv.z,oacc[10]); oacc[11]=fmaf(a2,vv.w,oacc[11]);
        oacc[12]=fmaf(a3,vv.x,oacc[12]); oacc[13]=fmaf(a3,vv.y,oacc[13]);
        oacc[14]=fmaf(a3,vv.z,oacc[14]); oacc[15]=fmaf(a3,vv.w,oacc[15]);
    }
    #pragma unroll
    for (int r = 0; r < 4; r++) {
        float4* O4 = (float4*)(out + (((size_t)(b*T_ + t0 + i0 + r)*H_ + h) << 6) + c0);
        *O4 = make_float4(oacc[r*4], oacc[r*4+1], oacc[r*4+2], oacc[r*4+3]);
    }
}

// ===========================================================================
extern "C" void kernel_launch(void* const* d_in, const int* in_sizes, int n_in,
                              void* d_out, int out_size)
{
    const float* q       = (const float*)d_in[0];
    const float* k       = (const float*)d_in[1];
    const float* v       = (const float*)d_in[2];
    const float* graw    = (const float*)d_in[3];
    const float* beta    = (const float*)d_in[4];
    const float* A_log   = (const float*)d_in[5];
    const float* dt_bias = (const float*)d_in[6];
    float* out = (float*)d_out;

    cudaFuncSetAttribute(phase1_kernel,
        cudaFuncAttributeMaxDynamicSharedMemorySize, P1_BYTES);
    cudaFuncSetAttribute(phase3_kernel,
        cudaFuncAttributeMaxDynamicSharedMemorySize, P3_BYTES);

    phase1_kernel<<<NCHUNK, 256, P1_BYTES>>>(q, k, v, graw, beta, A_log, dt_bias);
    phase2_kernel<<<256, 32>>>();
    phase3_kernel<<<NCHUNK, 256, P3_BYTES>>>(out);
}

// round 7
// speedup vs baseline: 2.2186x; 1.0229x over previous
#include <cuda_runtime.h>
#include <cuda_bf16.h>
#include <math.h>

#define B_   2
#define T_   8192
#define H_   16
#define KD   32
#define VD   64
#define BT_  64
#define NT_  128
#define NCHUNK 4096   // B*H*NT

typedef unsigned long long ull;

__device__ __forceinline__ void fma2(ull& acc, ull a, ull b) {
    asm("fma.rn.f32x2 %0, %1, %2, %3;" : "=l"(acc) : "l"(a), "l"(b), "l"(acc));
}
__device__ __forceinline__ ull dup2(float x) {
    ull r; asm("mov.b64 %0, {%1, %2};" : "=l"(r) : "f"(x), "f"(x)); return r;
}
__device__ __forceinline__ float2 unpack2(ull v) {
    float2 r; asm("mov.b64 {%0, %1}, %2;" : "=f"(r.x), "=f"(r.y) : "l"(v)); return r;
}

// ------------------- device scratch (no allocation allowed) ---------------
__device__ float g_P [NCHUNK*KD*KD];
__device__ float g_C [NCHUNK*KD*VD];
__device__ float g_E [NCHUNK*KD];
__device__ float g_W [NCHUNK*BT_*KD];
__device__ float g_U [(size_t)NCHUNK*BT_*VD];
__device__ float g_QG[NCHUNK*BT_*KD];
__device__ float g_KD[NCHUNK*KD*BT_];
__device__ float g_S [(size_t)NCHUNK*KD*VD];

// ---------------- phase-1 smem layout (floats), 4-aligned strides ---------
#define P1_KQ   0                    // b*kg rows [64][36]
#define P1_KDT  2304                 // kd^T [32][68]
#define P1_V    4480                 // b*v [64][64]; gcum overlays [64][32]
#define P1_L    8576                 // L [64][68]
#define P1_B    12928                // beta [64]
#define P1_E    12992                // e [32]
#define P1_FLOATS 13024
#define P1_BYTES  (P1_FLOATS*4)      // 52096

// ---------------- phase-3 smem layout (floats) ----------------
#define P3_A    0                    // Aqk [64][68]
#define P3_KD2  4352                 // kd^T [32][68]; later S [32][64]
#define P3_WQ   6528                 // qg then w [64][36]
#define P3_VN   8832                 // u -> v_new [64][64]
#define P3_FLOATS 12928
#define P3_BYTES  (P3_FLOATS*4)      // 51712

// ===========================================================================
__global__ void __launch_bounds__(256, 4) phase1_kernel(
    const float* __restrict__ q, const float* __restrict__ k,
    const float* __restrict__ v, const float* __restrict__ graw,
    const float* __restrict__ beta, const float* __restrict__ A_log,
    const float* __restrict__ dt_bias)
{
    extern __shared__ float sm[];
    float* sKQ  = sm + P1_KQ;    // stride 36
    float* sKDT = sm + P1_KDT;   // stride 68
    float* sV   = sm + P1_V;     // stride 64
    float* sG   = sm + P1_V;     // overlay [64][32]
    float* sL   = sm + P1_L;     // stride 68
    float* sB   = sm + P1_B;
    float* sE   = sm + P1_E;

    const int cid  = blockIdx.x;
    const int pair = cid >> 7, c = cid & 127;
    const int b    = pair >> 4, h = pair & 15;
    const int t0   = c * BT_;
    const int tid  = threadIdx.x;
    const int warp = tid >> 5, lane = tid & 31;

    const float expA = __expf(A_log[h]);

    // ---- gate ----
    for (int idx = tid; idx < 512; idx += 256) {
        int i = idx >> 3, q4 = (idx & 7) << 2;
        float4 gr = *(const float4*)(graw + (((size_t)(b*T_ + t0 + i)*H_ + h) << 5) + q4);
        float4 db = *(const float4*)(dt_bias + h*KD + q4);
        float4 o;
        o.x = -expA*(fmaxf(gr.x+db.x,0.f) + log1pf(__expf(-fabsf(gr.x+db.x))));
        o.y = -expA*(fmaxf(gr.y+db.y,0.f) + log1pf(__expf(-fabsf(gr.y+db.y))));
        o.z = -expA*(fmaxf(gr.z+db.z,0.f) + log1pf(__expf(-fabsf(gr.z+db.z))));
        o.w = -expA*(fmaxf(gr.w+db.w,0.f) + log1pf(__expf(-fabsf(gr.w+db.w))));
        *(float4*)(sG + i*KD + q4) = o;
    }
    for (int i = tid; i < BT_; i += 256)
        sB[i] = beta[(size_t)(b*T_ + t0 + i)*H_ + h];
    __syncthreads();

    // ---- cumsum per k-column ----
    if (tid < KD) {
        float run = 0.f;
        #pragma unroll 8
        for (int i = 0; i < BT_; i++) {
            run += sG[i*KD + tid];
            sG[i*KD + tid] = fmaxf(run, -80.f);
        }
        sE[tid] = __expf(fmaxf(run, -80.f));
    }
    __syncthreads();

    // ---- k,q rows: b*kg -> sKQ, kd^T -> sKDT, qg -> g_QG ----
    for (int r = warp; r < BT_; r += 8) {
        float gc = sG[r*KD + lane];
        float eg = __expf(gc);

        float kv = k[((size_t)((b*T_+t0+r)*H_ + h) << 5) + lane];
        float ss = kv*kv;
        #pragma unroll
        for (int o = 16; o; o >>= 1) ss += __shfl_xor_sync(0xffffffffu, ss, o);
        float kn = kv / fmaxf(sqrtf(ss), 1e-6f);
        sKQ [r*36  + lane] = sB[r] * kn * eg;
        sKDT[lane*68 + r]  = kn * __expf(-gc);

        float qv = q[((size_t)((b*T_+t0+r)*H_+h) << 5) + lane];
        float qs = qv*qv;
        #pragma unroll
        for (int o = 16; o; o >>= 1) qs += __shfl_xor_sync(0xffffffffu, qs, o);
        float qn = 0.1767766952966369f * qv / fmaxf(sqrtf(qs), 1e-6f);
        g_QG[(size_t)cid*2048 + r*KD + lane] = qn * eg;
    }
    __syncthreads();   // sG dead

    // ---- b*v -> sV (overwrites sG) ----
    for (int idx = tid; idx < 1024; idx += 256) {
        int i = idx >> 4, c4 = (idx & 15) << 2;
        float4 vv = *(const float4*)(v + (((size_t)(b*T_+t0+i)*H_+h) << 6) + c4);
        float bi = sB[i];
        vv.x *= bi; vv.y *= bi; vv.z *= bi; vv.w *= bi;
        *(float4*)(sV + i*64 + c4) = vv;
    }

    const int i0 = (tid >> 4) << 2, j0 = (tid & 15) << 2;

    // ---- L = (b*kg) @ kd^T, f32x2 + k-unroll-4 ----
    {
        ull acc[8];
        #pragma unroll
        for (int r = 0; r < 8; r++) acc[r] = 0ull;
        #pragma unroll 2
        for (int kk = 0; kk < KD; kk += 4) {
            float A0[4], A1[4], A2[4], A3[4];
            *(float4*)A0 = *(const float4*)(sKQ + (i0+0)*36 + kk);
            *(float4*)A1 = *(const float4*)(sKQ + (i0+1)*36 + kk);
            *(float4*)A2 = *(const float4*)(sKQ + (i0+2)*36 + kk);
            *(float4*)A3 = *(const float4*)(sKQ + (i0+3)*36 + kk);
            #pragma unroll
            for (int t = 0; t < 4; t++) {
                ulonglong2 d = *(const ulonglong2*)(sKDT + (kk+t)*68 + j0);
                ull a;
                a = dup2(A0[t]); fma2(acc[0], a, d.x); fma2(acc[1], a, d.y);
                a = dup2(A1[t]); fma2(acc[2], a, d.x); fma2(acc[3], a, d.y);
                a = dup2(A2[t]); fma2(acc[4], a, d.x); fma2(acc[5], a, d.y);
                a = dup2(A3[t]); fma2(acc[6], a, d.x); fma2(acc[7], a, d.y);
            }
        }
        #pragma unroll
        for (int r = 0; r < 4; r++) {
            float2 p0 = unpack2(acc[r*2]), p1 = unpack2(acc[r*2+1]);
            *(float4*)(sL + (i0+r)*68 + j0) = make_float4(p0.x, p0.y, p1.x, p1.y);
        }
    }
    __syncthreads();

    // ---- blocked forward substitution on x = [sKQ(36) | sV(64)] ----
    #pragma unroll 1
    for (int blk = 0; blk < 4; ++blk) {
        const int r0 = blk << 4;
        if (blk) {
            // update rows r0..r0+15 by cols 0..r0: 16 rows x 24 col-groups
            #pragma unroll 1
            for (int item = tid; item < 384; item += 256) {
                const int row = r0 + (item / 24);
                const int cg  = item % 24;
                float* base; int strd, xcol;
                if (cg < 8) { base = sKQ; strd = 36; xcol = cg << 2; }
                else        { base = sV;  strd = 64; xcol = (cg - 8) << 2; }
                float acc[4];
                *(float4*)acc = *(const float4*)(base + row*strd + xcol);
                const float* Lr = sL + row*68;
                #pragma unroll 2
                for (int kx = 0; kx < r0; kx += 4) {
                    float Lv[4];
                    *(float4*)Lv = *(const float4*)(Lr + kx);
                    #pragma unroll
                    for (int t = 0; t < 4; t++) {
                        float a = Lv[t];
                        const float* xr = base + (kx+t)*strd + xcol;
                        acc[0] = fmaf(-a, xr[0], acc[0]);
                        acc[1] = fmaf(-a, xr[1], acc[1]);
                        acc[2] = fmaf(-a, xr[2], acc[2]);
                        acc[3] = fmaf(-a, xr[3], acc[3]);
                    }
                }
                *(float4*)(base + row*strd + xcol) = make_float4(acc[0],acc[1],acc[2],acc[3]);
            }
            __syncthreads();
        }
        // in-block solve, columns in registers (96 threads)
        if (tid < 96) {
            float xr[16];
            if (tid < 32) {
                #pragma unroll
                for (int i = 0; i < 16; i++) xr[i] = sKQ[(r0+i)*36 + tid];
            } else {
                const int cc = tid - 32;
                #pragma unroll
                for (int i = 0; i < 16; i++) xr[i] = sV[(r0+i)*64 + cc];
            }
            #pragma unroll
            for (int i = 1; i < 16; i++) {
                const float* Lr = sL + (r0+i)*68 + r0;
                #pragma unroll
                for (int j = 0; j < i; j++)
                    xr[i] = fmaf(-Lr[j], xr[j], xr[i]);
            }
            if (tid < 32) {
                #pragma unroll
                for (int i = 1; i < 16; i++) sKQ[(r0+i)*36 + tid] = xr[i];
            } else {
                const int cc = tid - 32;
                #pragma unroll
                for (int i = 1; i < 16; i++) sV[(r0+i)*64 + cc] = xr[i];
            }
        }
        __syncthreads();
    }
    // w in sKQ, u in sV

    // ---- P = e*(kd^T @ w), f32x2 ----
    {
        const int kk = tid >> 3, m0 = (tid & 7) << 2;
        ull acc0 = 0ull, acc1 = 0ull;
        #pragma unroll 2
        for (int i = 0; i < BT_; i += 4) {
            float D[4];
            *(float4*)D = *(const float4*)(sKDT + kk*68 + i);
            #pragma unroll
            for (int t = 0; t < 4; t++) {
                ulonglong2 w2 = *(const ulonglong2*)(sKQ + (i+t)*36 + m0);
                ull dd = dup2(D[t]);
                fma2(acc0, dd, w2.x); fma2(acc1, dd, w2.y);
            }
        }
        float e = sE[kk];
        float2 p0 = unpack2(acc0), p1 = unpack2(acc1);
        *(float4*)(g_P + (size_t)cid*1024 + kk*32 + m0) =
            make_float4(e*p0.x, e*p0.y, e*p1.x, e*p1.y);
    }
    // ---- C = e*(kd^T @ u), f32x2 ----
    {
        const int kk = tid >> 3, v0 = (tid & 7) << 3;
        ull acc[4] = {0ull,0ull,0ull,0ull};
        #pragma unroll 2
        for (int i = 0; i < BT_; i += 4) {
            float D[4];
            *(float4*)D = *(const float4*)(sKDT + kk*68 + i);
            #pragma unroll
            for (int t = 0; t < 4; t++) {
                ulonglong2 x0 = *(const ulonglong2*)(sV + (i+t)*64 + v0);
                ulonglong2 x1 = *(const ulonglong2*)(sV + (i+t)*64 + v0 + 4);
                ull dd = dup2(D[t]);
                fma2(acc[0], dd, x0.x); fma2(acc[1], dd, x0.y);
                fma2(acc[2], dd, x1.x); fma2(acc[3], dd, x1.y);
            }
        }
        float e = sE[kk];
        float* dst = g_C + (size_t)cid*2048 + kk*64 + v0;
        float2 a0 = unpack2(acc[0]), a1 = unpack2(acc[1]);
        float2 a2 = unpack2(acc[2]), a3 = unpack2(acc[3]);
        *(float4*)(dst)   = make_float4(e*a0.x, e*a0.y, e*a1.x, e*a1.y);
        *(float4*)(dst+4) = make_float4(e*a2.x, e*a2.y, e*a3.x, e*a3.y);
    }
    if (tid < KD) g_E[cid*KD + tid] = sE[tid];

    // ---- store w, u, kd^T ----
    for (int idx = tid; idx < 2048; idx += 256)
        g_W[(size_t)cid*2048 + idx] = sKQ[(idx >> 5)*36 + (idx & 31)];
    for (int idx = tid; idx < 1024; idx += 256) {
        int i = idx >> 4, c4 = (idx & 15) << 2;
        *(float4*)(g_U + (size_t)cid*4096 + i*64 + c4) =
            *(const float4*)(sV + i*64 + c4);
    }
    for (int idx = tid; idx < 512; idx += 256) {
        int kk = idx >> 4, c4 = (idx & 15) << 2;
        *(float4*)(g_KD + (size_t)cid*2048 + kk*64 + c4) =
            *(const float4*)(sKDT + kk*68 + c4);
    }
}

// ===========================================================================
// Phase 2: S_{t+1} = diag(e)S - P S + C.  1 warp per (pair, 8-col slice).
// ===========================================================================
#define P4C(arr, m) ( ((m)&3)==0 ? arr[(m)>>2].x : ((m)&3)==1 ? arr[(m)>>2].y \
                    : ((m)&3)==2 ? arr[(m)>>2].z : arr[(m)>>2].w )

__global__ void __launch_bounds__(32) phase2_kernel()
{
    const int p     = blockIdx.x >> 3;
    const int vbase = (blockIdx.x & 7) << 3;
    const int lane  = threadIdx.x;
    const size_t base = (size_t)p*128;

    float4 Pc[8], Pn[8], Cc[2], Cn[2];
    float  ec, en;
    float  s[8];
    #pragma unroll
    for (int j = 0; j < 8; j++) s[j] = 0.f;

    {
        const float4* Pp = (const float4*)(g_P + base*1024 + lane*32);
        #pragma unroll
        for (int r = 0; r < 8; r++) Pc[r] = Pp[r];
        const float4* Cp = (const float4*)(g_C + base*2048 + lane*64 + vbase);
        Cc[0] = Cp[0]; Cc[1] = Cp[1];
        ec = g_E[base*32 + lane];
    }

    #pragma unroll 1
    for (int t = 0; t < 128; t++) {
        const size_t cid = base + t;
        if (t + 1 < 128) {
            const size_t cid1 = cid + 1;
            const float4* Pp = (const float4*)(g_P + cid1*1024 + lane*32);
            #pragma unroll
            for (int r = 0; r < 8; r++) Pn[r] = Pp[r];
            const float4* Cp = (const float4*)(g_C + cid1*2048 + lane*64 + vbase);
            Cn[0] = Cp[0]; Cn[1] = Cp[1];
            en = g_E[cid1*32 + lane];
        }
        float4* Sp = (float4*)(g_S + cid*2048 + lane*64 + vbase);
        Sp[0] = make_float4(s[0], s[1], s[2], s[3]);
        Sp[1] = make_float4(s[4], s[5], s[6], s[7]);

        float acc[8];
        acc[0]=fmaf(ec,s[0],Cc[0].x); acc[1]=fmaf(ec,s[1],Cc[0].y);
        acc[2]=fmaf(ec,s[2],Cc[0].z); acc[3]=fmaf(ec,s[3],Cc[0].w);
        acc[4]=fmaf(ec,s[4],Cc[1].x); acc[5]=fmaf(ec,s[5],Cc[1].y);
        acc[6]=fmaf(ec,s[6],Cc[1].z); acc[7]=fmaf(ec,s[7],Cc[1].w);

        #pragma unroll
        for (int m = 0; m < 32; m++) {
            float pm = P4C(Pc, m);
            #pragma unroll
            for (int j = 0; j < 8; j++)
                acc[j] = fmaf(-pm, __shfl_sync(0xffffffffu, s[j], m), acc[j]);
        }
        #pragma unroll
        for (int j = 0; j < 8; j++) s[j] = acc[j];
        #pragma unroll
        for (int r = 0; r < 8; r++) Pc[r] = Pn[r];
        Cc[0] = Cn[0]; Cc[1] = Cn[1];
        ec = en;
    }
}

// ===========================================================================
// Phase 3: o = qg S + Aqk (u - w S)
// ===========================================================================
__global__ void __launch_bounds__(256, 4) phase3_kernel(float* __restrict__ out)
{
    extern __shared__ float sm[];
    float* sA  = sm + P3_A;     // stride 68
    float* sKD = sm + P3_KD2;   // stride 68; later sS stride 64
    float* sS  = sm + P3_KD2;
    float* sWQ = sm + P3_WQ;    // stride 36
    float* sVn = sm + P3_VN;    // stride 64

    const int cid  = blockIdx.x;
    const int pair = cid >> 7, c = cid & 127;
    const int b    = pair >> 4, h = pair & 15;
    const int t0   = c * BT_;
    const int tid  = threadIdx.x;

    const int i0 = (tid >> 4) << 2, c0 = (tid & 15) << 2;

    // ---- load qg, kd, u ----
    for (int idx = tid; idx < 512; idx += 256) {
        int i = idx >> 3, c4 = (idx & 7) << 2;
        *(float4*)(sWQ + i*36 + c4) =
            *(const float4*)(g_QG + (size_t)cid*2048 + i*32 + c4);
    }
    for (int idx = tid; idx < 512; idx += 256) {
        int kk = idx >> 4, c4 = (idx & 15) << 2;
        *(float4*)(sKD + kk*68 + c4) =
            *(const float4*)(g_KD + (size_t)cid*2048 + kk*64 + c4);
    }
    for (int idx = tid; idx < 1024; idx += 256) {
        int i = idx >> 4, c4 = (idx & 15) << 2;
        *(float4*)(sVn + i*64 + c4) =
            *(const float4*)(g_U + (size_t)cid*4096 + i*64 + c4);
    }
    __syncthreads();

    // ---- Aqk = qg @ kd^T (full; masked at use), f32x2 ----
    {
        ull acc[8];
        #pragma unroll
        for (int r = 0; r < 8; r++) acc[r] = 0ull;
        #pragma unroll 2
        for (int kk = 0; kk < KD; kk += 4) {
            float A0[4], A1[4], A2[4], A3[4];
            *(float4*)A0 = *(const float4*)(sWQ + (i0+0)*36 + kk);
            *(float4*)A1 = *(const float4*)(sWQ + (i0+1)*36 + kk);
            *(float4*)A2 = *(const float4*)(sWQ + (i0+2)*36 + kk);
            *(float4*)A3 = *(const float4*)(sWQ + (i0+3)*36 + kk);
            #pragma unroll
            for (int t = 0; t < 4; t++) {
                ulonglong2 d = *(const ulonglong2*)(sKD + (kk+t)*68 + c0);
                ull a;
                a = dup2(A0[t]); fma2(acc[0], a, d.x); fma2(acc[1], a, d.y);
                a = dup2(A1[t]); fma2(acc[2], a, d.x); fma2(acc[3], a, d.y);
                a = dup2(A2[t]); fma2(acc[4], a, d.x); fma2(acc[5], a, d.y);
                a = dup2(A3[t]); fma2(acc[6], a, d.x); fma2(acc[7], a, d.y);
            }
        }
        #pragma unroll
        for (int r = 0; r < 4; r++) {
            float2 p0 = unpack2(acc[r*2]), p1 = unpack2(acc[r*2+1]);
            *(float4*)(sA + (i0+r)*68 + c0) = make_float4(p0.x, p0.y, p1.x, p1.y);
        }
    }
    __syncthreads();   // sKD dead

    // ---- load S over sKD region ----
    for (int idx = tid; idx < 512; idx += 256) {
        int kk = idx >> 4, c4 = (idx & 15) << 2;
        *(float4*)(sS + kk*64 + c4) =
            *(const float4*)(g_S + (size_t)cid*2048 + kk*64 + c4);
    }
    __syncthreads();

    // ---- oacc = qg @ S (qg still resident), f32x2 ----
    ull oacc[8];
    #pragma unroll
    for (int r = 0; r < 8; r++) oacc[r] = 0ull;
    #pragma unroll 2
    for (int m = 0; m < KD; m += 4) {
        float A0[4], A1[4], A2[4], A3[4];
        *(float4*)A0 = *(const float4*)(sWQ + (i0+0)*36 + m);
        *(float4*)A1 = *(const float4*)(sWQ + (i0+1)*36 + m);
        *(float4*)A2 = *(const float4*)(sWQ + (i0+2)*36 + m);
        *(float4*)A3 = *(const float4*)(sWQ + (i0+3)*36 + m);
        #pragma unroll
        for (int t = 0; t < 4; t++) {
            ulonglong2 sv = *(const ulonglong2*)(sS + (m+t)*64 + c0);
            ull a;
            a = dup2(A0[t]); fma2(oacc[0], a, sv.x); fma2(oacc[1], a, sv.y);
            a = dup2(A1[t]); fma2(oacc[2], a, sv.x); fma2(oacc[3], a, sv.y);
            a = dup2(A2[t]); fma2(oacc[4], a, sv.x); fma2(oacc[5], a, sv.y);
            a = dup2(A3[t]); fma2(oacc[6], a, sv.x); fma2(oacc[7], a, sv.y);
        }
    }
    __syncthreads();   // qg reads done

    // ---- load w over qg ----
    for (int idx = tid; idx < 512; idx += 256) {
        int i = idx >> 3, c4 = (idx & 7) << 2;
        *(float4*)(sWQ + i*36 + c4) =
            *(const float4*)(g_W + (size_t)cid*2048 + i*32 + c4);
    }
    __syncthreads();

    // ---- v_new = u - w @ S (tiles private, in place), f32x2 ----
    {
        ull acc[8];
        #pragma unroll
        for (int r = 0; r < 4; r++) {
            ulonglong2 u2 = *(const ulonglong2*)(sVn + (i0+r)*64 + c0);
            acc[r*2] = u2.x; acc[r*2+1] = u2.y;
        }
        #pragma unroll 2
        for (int m = 0; m < KD; m += 4) {
            float A0[4], A1[4], A2[4], A3[4];
            *(float4*)A0 = *(const float4*)(sWQ + (i0+0)*36 + m);
            *(float4*)A1 = *(const float4*)(sWQ + (i0+1)*36 + m);
            *(float4*)A2 = *(const float4*)(sWQ + (i0+2)*36 + m);
            *(float4*)A3 = *(const float4*)(sWQ + (i0+3)*36 + m);
            #pragma unroll
            for (int t = 0; t < 4; t++) {
                ulonglong2 sv = *(const ulonglong2*)(sS + (m+t)*64 + c0);
                ull a;
                a = dup2(-A0[t]); fma2(acc[0], a, sv.x); fma2(acc[1], a, sv.y);
                a = dup2(-A1[t]); fma2(acc[2], a, sv.x); fma2(acc[3], a, sv.y);
                a = dup2(-A2[t]); fma2(acc[4], a, sv.x); fma2(acc[5], a, sv.y);
                a = dup2(-A3[t]); fma2(acc[6], a, sv.x); fma2(acc[7], a, sv.y);
            }
        }
        #pragma unroll
        for (int r = 0; r < 4; r++) {
            ulonglong2 u2; u2.x = acc[r*2]; u2.y = acc[r*2+1];
            *(ulonglong2*)(sVn + (i0+r)*64 + c0) = u2;
        }
    }
    __syncthreads();

    // ---- oacc += Aqk @ v_new (lower-incl mask), f32x2 ----
    {
        // full groups jg*4 < i0
        #pragma unroll 1
        for (int jg = 0; jg < (i0 >> 2); jg++) {
            const int jb = jg << 2;
            float A0[4], A1[4], A2[4], A3[4];
            *(float4*)A0 = *(const float4*)(sA + (i0+0)*68 + jb);
            *(float4*)A1 = *(const float4*)(sA + (i0+1)*68 + jb);
            *(float4*)A2 = *(const float4*)(sA + (i0+2)*68 + jb);
            *(float4*)A3 = *(const float4*)(sA + (i0+3)*68 + jb);
            #pragma unroll
            for (int t = 0; t < 4; t++) {
                ulonglong2 vv = *(const ulonglong2*)(sVn + (jb+t)*64 + c0);
                ull a;
                a = dup2(A0[t]); fma2(oacc[0], a, vv.x); fma2(oacc[1], a, vv.y);
                a = dup2(A1[t]); fma2(oacc[2], a, vv.x); fma2(oacc[3], a, vv.y);
                a = dup2(A2[t]); fma2(oacc[4], a, vv.x); fma2(oacc[5], a, vv.y);
                a = dup2(A3[t]); fma2(oacc[6], a, vv.x); fma2(oacc[7], a, vv.y);
            }
        }
        // diagonal group jb == i0: row r uses j = i0+t with t <= r
        {
            const int jb = i0;
            float A0[4], A1[4], A2[4], A3[4];
            *(float4*)A0 = *(const float4*)(sA + (i0+0)*68 + jb);
            *(float4*)A1 = *(const float4*)(sA + (i0+1)*68 + jb);
            *(float4*)A2 = *(const float4*)(sA + (i0+2)*68 + jb);
            *(float4*)A3 = *(const float4*)(sA + (i0+3)*68 + jb);
            A0[1]=A0[2]=A0[3]=0.f; A1[2]=A1[3]=0.f; A2[3]=0.f;
            #pragma unroll
            for (int t = 0; t < 4; t++) {
                ulonglong2 vv = *(const ulonglong2*)(sVn + (jb+t)*64 + c0);
                ull a;
                a = dup2(A0[t]); fma2(oacc[0], a, vv.x); fma2(oacc[1], a, vv.y);
                a = dup2(A1[t]); fma2(oacc[2], a, vv.x); fma2(oacc[3], a, vv.y);
                a = dup2(A2[t]); fma2(oacc[4], a, vv.x); fma2(oacc[5], a, vv.y);
                a = dup2(A3[t]); fma2(oacc[6], a, vv.x); fma2(oacc[7], a, vv.y);
            }
        }
    }

    #pragma unroll
    for (int r = 0; r < 4; r++) {
        float2 p0 = unpack2(oacc[r*2]), p1 = unpack2(oacc[r*2+1]);
        float4* O4 = (float4*)(out + (((size_t)(b*T_ + t0 + i0 + r)*H_ + h) << 6) + c0);
        *O4 = make_float4(p0.x, p0.y, p1.x, p1.y);
    }
}

// ===========================================================================
extern "C" void kernel_launch(void* const* d_in, const int* in_sizes, int n_in,
                              void* d_out, int out_size)
{
    const float* q       = (const float*)d_in[0];
    const float* k       = (const float*)d_in[1];
    const float* v       = (const float*)d_in[2];
    const float* graw    = (const float*)d_in[3];
    const float* beta    = (const float*)d_in[4];
    const float* A_log   = (const float*)d_in[5];
    const float* dt_bias = (const float*)d_in[6];
    float* out = (float*)d_out;

    cudaFuncSetAttribute(phase1_kernel,
        cudaFuncAttributeMaxDynamicSharedMemorySize, P1_BYTES);
    cudaFuncSetAttribute(phase3_kernel,
        cudaFuncAttributeMaxDynamicSharedMemorySize, P3_BYTES);

    phase1_kernel<<<NCHUNK, 256, P1_BYTES>>>(q, k, v, graw, beta, A_log, dt_bias);
    phase2_kernel<<<256, 32>>>();
    phase3_kernel<<<NCHUNK, 256, P3_BYTES>>>(out);
}

// round 8
// speedup vs baseline: 2.2777x; 1.0267x over previous
#include <cuda_runtime.h>
#include <cuda_bf16.h>
#include <math.h>

#define B_   2
#define T_   8192
#define H_   16
#define KD   32
#define VD   64
#define BT_  64
#define NT_  128
#define NCHUNK 4096   // B*H*NT

typedef unsigned long long ull;

__device__ __forceinline__ void fma2(ull& acc, ull a, ull b) {
    asm("fma.rn.f32x2 %0, %1, %2, %3;" : "=l"(acc) : "l"(a), "l"(b), "l"(acc));
}
__device__ __forceinline__ ull dup2(float x) {
    ull r; asm("mov.b64 %0, {%1, %2};" : "=l"(r) : "f"(x), "f"(x)); return r;
}
__device__ __forceinline__ float2 unpack2(ull v) {
    float2 r; asm("mov.b64 {%0, %1}, %2;" : "=f"(r.x), "=f"(r.y) : "l"(v)); return r;
}

// ------------------- device scratch (no allocation allowed) ---------------
__device__ float g_P [NCHUNK*KD*KD];
__device__ float g_C [NCHUNK*KD*VD];
__device__ float g_E [NCHUNK*KD];
__device__ float g_W [NCHUNK*BT_*KD];
__device__ float g_U [(size_t)NCHUNK*BT_*VD];
__device__ float g_QG[NCHUNK*BT_*KD];
__device__ float g_KD[NCHUNK*BT_*KD];           // kdR row-major [64][32]
__device__ float g_S [(size_t)NCHUNK*KD*VD];

// ---------------- phase-1 smem layout (floats) ----------------
#define P1_KQ   0        // b*kg [64][36]
#define P1_KD   2304     // kdR  [64][36]
#define P1_V    4608     // b*v [64][64]; gcum overlays [64][32]
#define P1_L    8704     // L [64][68]
#define P1_B    13056    // beta [64]
#define P1_E    13120    // e [32]
#define P1_BS   13152    // block sums [8][32]
#define P1_FLOATS 13408
#define P1_BYTES  (P1_FLOATS*4)      // 53632

// ---------------- phase-3 smem layout (floats) ----------------
#define P3_A    0        // Aqk [64][68]
#define P3_KD2  4352     // kdR [64][36]; later S [32][64]
#define P3_WQ   6656     // qg then w [64][36]
#define P3_VN   8960     // u -> v_new [64][64]
#define P3_FLOATS 13056
#define P3_BYTES  (P3_FLOATS*4)      // 52224

// ===========================================================================
__global__ void __launch_bounds__(256, 4) phase1_kernel(
    const float* __restrict__ q, const float* __restrict__ k,
    const float* __restrict__ v, const float* __restrict__ graw,
    const float* __restrict__ beta, const float* __restrict__ A_log,
    const float* __restrict__ dt_bias)
{
    extern __shared__ float sm[];
    float* sKQ = sm + P1_KQ;    // stride 36
    float* sKD = sm + P1_KD;    // stride 36 (row-major kdR)
    float* sV  = sm + P1_V;     // stride 64
    float* sG  = sm + P1_V;     // overlay [64][32]
    float* sL  = sm + P1_L;     // stride 68
    float* sB  = sm + P1_B;
    float* sE  = sm + P1_E;
    float* sBS = sm + P1_BS;

    const int cid  = blockIdx.x;
    const int pair = cid >> 7, c = cid & 127;
    const int b    = pair >> 4, h = pair & 15;
    const int t0   = c * BT_;
    const int tid  = threadIdx.x;
    const int warp = tid >> 5, lane = tid & 31;

    const float expA = __expf(A_log[h]);

    // ---- gate ----
    for (int idx = tid; idx < 512; idx += 256) {
        int i = idx >> 3, q4 = (idx & 7) << 2;
        float4 gr = *(const float4*)(graw + (((size_t)(b*T_ + t0 + i)*H_ + h) << 5) + q4);
        float4 db = *(const float4*)(dt_bias + h*KD + q4);
        float4 o;
        o.x = -expA*(fmaxf(gr.x+db.x,0.f) + log1pf(__expf(-fabsf(gr.x+db.x))));
        o.y = -expA*(fmaxf(gr.y+db.y,0.f) + log1pf(__expf(-fabsf(gr.y+db.y))));
        o.z = -expA*(fmaxf(gr.z+db.z,0.f) + log1pf(__expf(-fabsf(gr.z+db.z))));
        o.w = -expA*(fmaxf(gr.w+db.w,0.f) + log1pf(__expf(-fabsf(gr.w+db.w))));
        *(float4*)(sG + i*KD + q4) = o;
    }
    for (int i = tid; i < BT_; i += 256)
        sB[i] = beta[(size_t)(b*T_ + t0 + i)*H_ + h];
    __syncthreads();

    // ---- parallel cumsum: 8-row local scans + block prefix ----
    {
        const int blk = tid >> 5, kk = tid & 31;
        float pref[8];
        float run = 0.f;
        #pragma unroll
        for (int t = 0; t < 8; t++) {
            run += sG[(blk*8 + t)*KD + kk];
            pref[t] = run;
        }
        sBS[blk*32 + kk] = run;
        __syncthreads();
        float pre = 0.f;
        #pragma unroll
        for (int j = 0; j < 7; j++)
            if (j < blk) pre += sBS[j*32 + kk];
        #pragma unroll
        for (int t = 0; t < 8; t++)
            sG[(blk*8 + t)*KD + kk] = fmaxf(pre + pref[t], -80.f);
        if (blk == 7) sE[kk] = __expf(fmaxf(pre + pref[7], -80.f));
    }
    __syncthreads();

    // ---- k,q rows: b*kg -> sKQ, kdR -> sKD, qg -> g_QG ----
    for (int r = warp; r < BT_; r += 8) {
        float gc = sG[r*KD + lane];
        float eg = __expf(gc);

        float kv = k[((size_t)((b*T_+t0+r)*H_ + h) << 5) + lane];
        float ss = kv*kv;
        #pragma unroll
        for (int o = 16; o; o >>= 1) ss += __shfl_xor_sync(0xffffffffu, ss, o);
        float kn = kv / fmaxf(sqrtf(ss), 1e-6f);
        sKQ[r*36 + lane] = sB[r] * kn * eg;
        sKD[r*36 + lane] = kn * __expf(-gc);

        float qv = q[((size_t)((b*T_+t0+r)*H_+h) << 5) + lane];
        float qs = qv*qv;
        #pragma unroll
        for (int o = 16; o; o >>= 1) qs += __shfl_xor_sync(0xffffffffu, qs, o);
        float qn = 0.1767766952966369f * qv / fmaxf(sqrtf(qs), 1e-6f);
        g_QG[(size_t)cid*2048 + r*KD + lane] = qn * eg;
    }
    __syncthreads();   // sG dead

    // ---- b*v -> sV (overwrites sG) ----
    for (int idx = tid; idx < 1024; idx += 256) {
        int i = idx >> 4, c4 = (idx & 15) << 2;
        float4 vv = *(const float4*)(v + (((size_t)(b*T_+t0+i)*H_+h) << 6) + c4);
        float bi = sB[i];
        vv.x *= bi; vv.y *= bi; vv.z *= bi; vv.w *= bi;
        *(float4*)(sV + i*64 + c4) = vv;
    }

    // ---- L = (b*kg) @ kdR^T, NT scalar 4x4 ----
    {
        const int i0 = (tid >> 4) << 2, j0 = (tid & 15) << 2;
        float acc[16];
        #pragma unroll
        for (int r = 0; r < 16; r++) acc[r] = 0.f;
        #pragma unroll 1
        for (int kk = 0; kk < KD; kk += 4) {
            float A[4][4], Bv[4][4];
            #pragma unroll
            for (int r = 0; r < 4; r++)
                *(float4*)A[r] = *(const float4*)(sKQ + (i0+r)*36 + kk);
            #pragma unroll
            for (int cc = 0; cc < 4; cc++)
                *(float4*)Bv[cc] = *(const float4*)(sKD + (j0+cc)*36 + kk);
            #pragma unroll
            for (int r = 0; r < 4; r++)
                #pragma unroll
                for (int cc = 0; cc < 4; cc++) {
                    acc[r*4+cc] = fmaf(A[r][0], Bv[cc][0], acc[r*4+cc]);
                    acc[r*4+cc] = fmaf(A[r][1], Bv[cc][1], acc[r*4+cc]);
                    acc[r*4+cc] = fmaf(A[r][2], Bv[cc][2], acc[r*4+cc]);
                    acc[r*4+cc] = fmaf(A[r][3], Bv[cc][3], acc[r*4+cc]);
                }
        }
        #pragma unroll
        for (int r = 0; r < 4; r++)
            *(float4*)(sL + (i0+r)*68 + j0) =
                make_float4(acc[r*4], acc[r*4+1], acc[r*4+2], acc[r*4+3]);
    }
    __syncthreads();

    // ---- blocked forward substitution on x = [sKQ(36) | sV(64)] ----
    #pragma unroll 1
    for (int blk = 0; blk < 4; ++blk) {
        const int r0 = blk << 4;
        if (blk) {
            // panel update: rows r0..r0+15 -= L[:,0..r0) @ x ; 96 threads, 4x4 f32x2
            if (tid < 96) {
                const int rg = tid & 3, cgs = tid >> 2;
                float* xb; int strd, xc;
                if (cgs < 8) { xb = sKQ; strd = 36; xc = cgs << 2; }
                else         { xb = sV;  strd = 64; xc = (cgs - 8) << 2; }
                const int rb = r0 + (rg << 2);
                ull acc[8];
                #pragma unroll
                for (int r = 0; r < 4; r++) {
                    ulonglong2 u2 = *(const ulonglong2*)(xb + (rb+r)*strd + xc);
                    acc[r*2] = u2.x; acc[r*2+1] = u2.y;
                }
                #pragma unroll 1
                for (int kx = 0; kx < r0; kx += 4) {
                    float Lv[4][4];
                    #pragma unroll
                    for (int r = 0; r < 4; r++)
                        *(float4*)Lv[r] = *(const float4*)(sL + (rb+r)*68 + kx);
                    #pragma unroll
                    for (int t = 0; t < 4; t++) {
                        ulonglong2 bv = *(const ulonglong2*)(xb + (kx+t)*strd + xc);
                        #pragma unroll
                        for (int r = 0; r < 4; r++) {
                            ull a = dup2(-Lv[r][t]);
                            fma2(acc[r*2], a, bv.x); fma2(acc[r*2+1], a, bv.y);
                        }
                    }
                }
                #pragma unroll
                for (int r = 0; r < 4; r++) {
                    ulonglong2 u2; u2.x = acc[r*2]; u2.y = acc[r*2+1];
                    *(ulonglong2*)(xb + (rb+r)*strd + xc) = u2;
                }
            }
            __syncthreads();
        }
        // in-block solve, columns in registers (96 threads)
        if (tid < 96) {
            float xr[16];
            if (tid < 32) {
                #pragma unroll
                for (int i = 0; i < 16; i++) xr[i] = sKQ[(r0+i)*36 + tid];
            } else {
                const int cc = tid - 32;
                #pragma unroll
                for (int i = 0; i < 16; i++) xr[i] = sV[(r0+i)*64 + cc];
            }
            #pragma unroll
            for (int i = 1; i < 16; i++) {
                const float* Lr = sL + (r0+i)*68 + r0;
                #pragma unroll
                for (int j = 0; j < i; j++)
                    xr[i] = fmaf(-Lr[j], xr[j], xr[i]);
            }
            if (tid < 32) {
                #pragma unroll
                for (int i = 1; i < 16; i++) sKQ[(r0+i)*36 + tid] = xr[i];
            } else {
                const int cc = tid - 32;
                #pragma unroll
                for (int i = 1; i < 16; i++) sV[(r0+i)*64 + cc] = xr[i];
            }
        }
        __syncthreads();
    }
    // w in sKQ, u in sV

    // ---- fused P|C = e * (kdR^T @ [w|u]) : outer-product over i ----
    if (tid < 192) {
        const int kkg = tid & 7, cg = tid >> 3;   // kk0 = kkg*4, col0 = cg*4
        const int kk0 = kkg << 2;
        float* xb; int strd, xc;
        if (cg < 8) { xb = sKQ; strd = 36; xc = cg << 2; }
        else        { xb = sV;  strd = 64; xc = (cg - 8) << 2; }
        ull acc[8];
        #pragma unroll
        for (int r = 0; r < 8; r++) acc[r] = 0ull;
        #pragma unroll 4
        for (int i = 0; i < BT_; i++) {
            float a4[4];
            *(float4*)a4 = *(const float4*)(sKD + i*36 + kk0);
            ulonglong2 bv = *(const ulonglong2*)(xb + i*strd + xc);
            #pragma unroll
            for (int r = 0; r < 4; r++) {
                ull ad = dup2(a4[r]);
                fma2(acc[r*2], ad, bv.x); fma2(acc[r*2+1], ad, bv.y);
            }
        }
        #pragma unroll
        for (int r = 0; r < 4; r++) {
            float e = sE[kk0 + r];
            float2 p0 = unpack2(acc[r*2]), p1 = unpack2(acc[r*2+1]);
            float4 val = make_float4(e*p0.x, e*p0.y, e*p1.x, e*p1.y);
            if (cg < 8)
                *(float4*)(g_P + (size_t)cid*1024 + (kk0+r)*32 + (cg<<2)) = val;
            else
                *(float4*)(g_C + (size_t)cid*2048 + (kk0+r)*64 + ((cg-8)<<2)) = val;
        }
    }
    if (tid < KD) g_E[cid*KD + tid] = sE[tid];

    // ---- store w, u, kdR ----
    for (int idx = tid; idx < 512; idx += 256) {
        int i = idx >> 3, c4 = (idx & 7) << 2;
        *(float4*)(g_W + (size_t)cid*2048 + i*32 + c4) =
            *(const float4*)(sKQ + i*36 + c4);
    }
    for (int idx = tid; idx < 1024; idx += 256) {
        int i = idx >> 4, c4 = (idx & 15) << 2;
        *(float4*)(g_U + (size_t)cid*4096 + i*64 + c4) =
            *(const float4*)(sV + i*64 + c4);
    }
    for (int idx = tid; idx < 512; idx += 256) {
        int i = idx >> 3, c4 = (idx & 7) << 2;
        *(float4*)(g_KD + (size_t)cid*2048 + i*32 + c4) =
            *(const float4*)(sKD + i*36 + c4);
    }
}

// ===========================================================================
// Phase 2: S_{t+1} = diag(e)S - P S + C.  1 warp per (pair, 8-col slice).
// ===========================================================================
#define P4C(arr, m) ( ((m)&3)==0 ? arr[(m)>>2].x : ((m)&3)==1 ? arr[(m)>>2].y \
                    : ((m)&3)==2 ? arr[(m)>>2].z : arr[(m)>>2].w )

__global__ void __launch_bounds__(32) phase2_kernel()
{
    const int p     = blockIdx.x >> 3;
    const int vbase = (blockIdx.x & 7) << 3;
    const int lane  = threadIdx.x;
    const size_t base = (size_t)p*128;

    float4 Pc[8], Pn[8], Cc[2], Cn[2];
    float  ec, en;
    float  s[8];
    #pragma unroll
    for (int j = 0; j < 8; j++) s[j] = 0.f;

    {
        const float4* Pp = (const float4*)(g_P + base*1024 + lane*32);
        #pragma unroll
        for (int r = 0; r < 8; r++) Pc[r] = Pp[r];
        const float4* Cp = (const float4*)(g_C + base*2048 + lane*64 + vbase);
        Cc[0] = Cp[0]; Cc[1] = Cp[1];
        ec = g_E[base*32 + lane];
    }

    #pragma unroll 1
    for (int t = 0; t < 128; t++) {
        const size_t cid = base + t;
        if (t + 1 < 128) {
            const size_t cid1 = cid + 1;
            const float4* Pp = (const float4*)(g_P + cid1*1024 + lane*32);
            #pragma unroll
            for (int r = 0; r < 8; r++) Pn[r] = Pp[r];
            const float4* Cp = (const float4*)(g_C + cid1*2048 + lane*64 + vbase);
            Cn[0] = Cp[0]; Cn[1] = Cp[1];
            en = g_E[cid1*32 + lane];
        }
        float4* Sp = (float4*)(g_S + cid*2048 + lane*64 + vbase);
        Sp[0] = make_float4(s[0], s[1], s[2], s[3]);
        Sp[1] = make_float4(s[4], s[5], s[6], s[7]);

        float acc[8];
        acc[0]=fmaf(ec,s[0],Cc[0].x); acc[1]=fmaf(ec,s[1],Cc[0].y);
        acc[2]=fmaf(ec,s[2],Cc[0].z); acc[3]=fmaf(ec,s[3],Cc[0].w);
        acc[4]=fmaf(ec,s[4],Cc[1].x); acc[5]=fmaf(ec,s[5],Cc[1].y);
        acc[6]=fmaf(ec,s[6],Cc[1].z); acc[7]=fmaf(ec,s[7],Cc[1].w);

        #pragma unroll
        for (int m = 0; m < 32; m++) {
            float pm = P4C(Pc, m);
            #pragma unroll
            for (int j = 0; j < 8; j++)
                acc[j] = fmaf(-pm, __shfl_sync(0xffffffffu, s[j], m), acc[j]);
        }
        #pragma unroll
        for (int j = 0; j < 8; j++) s[j] = acc[j];
        #pragma unroll
        for (int r = 0; r < 8; r++) Pc[r] = Pn[r];
        Cc[0] = Cn[0]; Cc[1] = Cn[1];
        ec = en;
    }
}

// ===========================================================================
// Phase 3: o = qg S + Aqk (u - w S)
// ===========================================================================
__global__ void __launch_bounds__(256, 4) phase3_kernel(float* __restrict__ out)
{
    extern __shared__ float sm[];
    float* sA  = sm + P3_A;     // stride 68
    float* sKD = sm + P3_KD2;   // kdR [64][36]; later S [32][64]
    float* sS  = sm + P3_KD2;
    float* sWQ = sm + P3_WQ;    // stride 36
    float* sVn = sm + P3_VN;    // stride 64

    const int cid  = blockIdx.x;
    const int pair = cid >> 7, c = cid & 127;
    const int b    = pair >> 4, h = pair & 15;
    const int t0   = c * BT_;
    const int tid  = threadIdx.x;

    const int i0 = (tid >> 4) << 2, c0 = (tid & 15) << 2;

    // ---- load qg, kdR, u ----
    for (int idx = tid; idx < 512; idx += 256) {
        int i = idx >> 3, c4 = (idx & 7) << 2;
        *(float4*)(sWQ + i*36 + c4) =
            *(const float4*)(g_QG + (size_t)cid*2048 + i*32 + c4);
    }
    for (int idx = tid; idx < 512; idx += 256) {
        int i = idx >> 3, c4 = (idx & 7) << 2;
        *(float4*)(sKD + i*36 + c4) =
            *(const float4*)(g_KD + (size_t)cid*2048 + i*32 + c4);
    }
    for (int idx = tid; idx < 1024; idx += 256) {
        int i = idx >> 4, c4 = (idx & 15) << 2;
        *(float4*)(sVn + i*64 + c4) =
            *(const float4*)(g_U + (size_t)cid*4096 + i*64 + c4);
    }
    __syncthreads();

    // ---- Aqk = qg @ kdR^T, NT scalar 4x4 (full; masked at use) ----
    {
        float acc[16];
        #pragma unroll
        for (int r = 0; r < 16; r++) acc[r] = 0.f;
        #pragma unroll 1
        for (int kk = 0; kk < KD; kk += 4) {
            float A[4][4], Bv[4][4];
            #pragma unroll
            for (int r = 0; r < 4; r++)
                *(float4*)A[r] = *(const float4*)(sWQ + (i0+r)*36 + kk);
            #pragma unroll
            for (int cc = 0; cc < 4; cc++)
                *(float4*)Bv[cc] = *(const float4*)(sKD + (c0+cc)*36 + kk);
            #pragma unroll
            for (int r = 0; r < 4; r++)
                #pragma unroll
                for (int cc = 0; cc < 4; cc++) {
                    acc[r*4+cc] = fmaf(A[r][0], Bv[cc][0], acc[r*4+cc]);
                    acc[r*4+cc] = fmaf(A[r][1], Bv[cc][1], acc[r*4+cc]);
                    acc[r*4+cc] = fmaf(A[r][2], Bv[cc][2], acc[r*4+cc]);
                    acc[r*4+cc] = fmaf(A[r][3], Bv[cc][3], acc[r*4+cc]);
                }
        }
        #pragma unroll
        for (int r = 0; r < 4; r++)
            *(float4*)(sA + (i0+r)*68 + c0) =
                make_float4(acc[r*4], acc[r*4+1], acc[r*4+2], acc[r*4+3]);
    }
    __syncthreads();   // sKD dead

    // ---- load S over sKD region ----
    for (int idx = tid; idx < 512; idx += 256) {
        int kk = idx >> 4, c4 = (idx & 15) << 2;
        *(float4*)(sS + kk*64 + c4) =
            *(const float4*)(g_S + (size_t)cid*2048 + kk*64 + c4);
    }
    __syncthreads();

    // ---- oacc = qg @ S (qg still resident), f32x2 ----
    ull oacc[8];
    #pragma unroll
    for (int r = 0; r < 8; r++) oacc[r] = 0ull;
    #pragma unroll 2
    for (int m = 0; m < KD; m += 4) {
        float A0[4], A1[4], A2[4], A3[4];
        *(float4*)A0 = *(const float4*)(sWQ + (i0+0)*36 + m);
        *(float4*)A1 = *(const float4*)(sWQ + (i0+1)*36 + m);
        *(float4*)A2 = *(const float4*)(sWQ + (i0+2)*36 + m);
        *(float4*)A3 = *(const float4*)(sWQ + (i0+3)*36 + m);
        #pragma unroll
        for (int t = 0; t < 4; t++) {
            ulonglong2 sv = *(const ulonglong2*)(sS + (m+t)*64 + c0);
            ull a;
            a = dup2(A0[t]); fma2(oacc[0], a, sv.x); fma2(oacc[1], a, sv.y);
            a = dup2(A1[t]); fma2(oacc[2], a, sv.x); fma2(oacc[3], a, sv.y);
            a = dup2(A2[t]); fma2(oacc[4], a, sv.x); fma2(oacc[5], a, sv.y);
            a = dup2(A3[t]); fma2(oacc[6], a, sv.x); fma2(oacc[7], a, sv.y);
        }
    }
    __syncthreads();   // qg reads done

    // ---- load w over qg ----
    for (int idx = tid; idx < 512; idx += 256) {
        int i = idx >> 3, c4 = (idx & 7) << 2;
        *(float4*)(sWQ + i*36 + c4) =
            *(const float4*)(g_W + (size_t)cid*2048 + i*32 + c4);
    }
    __syncthreads();

    // ---- v_new = u - w @ S (tiles private, in place), f32x2 ----
    {
        ull acc[8];
        #pragma unroll
        for (int r = 0; r < 4; r++) {
            ulonglong2 u2 = *(const ulonglong2*)(sVn + (i0+r)*64 + c0);
            acc[r*2] = u2.x; acc[r*2+1] = u2.y;
        }
        #pragma unroll 2
        for (int m = 0; m < KD; m += 4) {
            float A0[4], A1[4], A2[4], A3[4];
            *(float4*)A0 = *(const float4*)(sWQ + (i0+0)*36 + m);
            *(float4*)A1 = *(const float4*)(sWQ + (i0+1)*36 + m);
            *(float4*)A2 = *(const float4*)(sWQ + (i0+2)*36 + m);
            *(float4*)A3 = *(const float4*)(sWQ + (i0+3)*36 + m);
            #pragma unroll
            for (int t = 0; t < 4; t++) {
                ulonglong2 sv = *(const ulonglong2*)(sS + (m+t)*64 + c0);
                ull a;
                a = dup2(-A0[t]); fma2(acc[0], a, sv.x); fma2(acc[1], a, sv.y);
                a = dup2(-A1[t]); fma2(acc[2], a, sv.x); fma2(acc[3], a, sv.y);
                a = dup2(-A2[t]); fma2(acc[4], a, sv.x); fma2(acc[5], a, sv.y);
                a = dup2(-A3[t]); fma2(acc[6], a, sv.x); fma2(acc[7], a, sv.y);
            }
        }
        #pragma unroll
        for (int r = 0; r < 4; r++) {
            ulonglong2 u2; u2.x = acc[r*2]; u2.y = acc[r*2+1];
            *(ulonglong2*)(sVn + (i0+r)*64 + c0) = u2;
        }
    }
    __syncthreads();

    // ---- oacc += Aqk @ v_new (lower-incl mask), f32x2 ----
    {
        #pragma unroll 1
        for (int jg = 0; jg < (i0 >> 2); jg++) {
            const int jb = jg << 2;
            float A0[4], A1[4], A2[4], A3[4];
            *(float4*)A0 = *(const float4*)(sA + (i0+0)*68 + jb);
            *(float4*)A1 = *(const float4*)(sA + (i0+1)*68 + jb);
            *(float4*)A2 = *(const float4*)(sA + (i0+2)*68 + jb);
            *(float4*)A3 = *(const float4*)(sA + (i0+3)*68 + jb);
            #pragma unroll
            for (int t = 0; t < 4; t++) {
                ulonglong2 vv = *(const ulonglong2*)(sVn + (jb+t)*64 + c0);
                ull a;
                a = dup2(A0[t]); fma2(oacc[0], a, vv.x); fma2(oacc[1], a, vv.y);
                a = dup2(A1[t]); fma2(oacc[2], a, vv.x); fma2(oacc[3], a, vv.y);
                a = dup2(A2[t]); fma2(oacc[4], a, vv.x); fma2(oacc[5], a, vv.y);
                a = dup2(A3[t]); fma2(oacc[6], a, vv.x); fma2(oacc[7], a, vv.y);
            }
        }
        {
            const int jb = i0;
            float A0[4], A1[4], A2[4], A3[4];
            *(float4*)A0 = *(const float4*)(sA + (i0+0)*68 + jb);
            *(float4*)A1 = *(const float4*)(sA + (i0+1)*68 + jb);
            *(float4*)A2 = *(const float4*)(sA + (i0+2)*68 + jb);
            *(float4*)A3 = *(const float4*)(sA + (i0+3)*68 + jb);
            A0[1]=A0[2]=A0[3]=0.f; A1[2]=A1[3]=0.f; A2[3]=0.f;
            #pragma unroll
            for (int t = 0; t < 4; t++) {
                ulonglong2 vv = *(const ulonglong2*)(sVn + (jb+t)*64 + c0);
                ull a;
                a = dup2(A0[t]); fma2(oacc[0], a, vv.x); fma2(oacc[1], a, vv.y);
                a = dup2(A1[t]); fma2(oacc[2], a, vv.x); fma2(oacc[3], a, vv.y);
                a = dup2(A2[t]); fma2(oacc[4], a, vv.x); fma2(oacc[5], a, vv.y);
                a = dup2(A3[t]); fma2(oacc[6], a, vv.x); fma2(oacc[7], a, vv.y);
            }
        }
    }

    #pragma unroll
    for (int r = 0; r < 4; r++) {
        float2 p0 = unpack2(oacc[r*2]), p1 = unpack2(oacc[r*2+1]);
        float4* O4 = (float4*)(out + (((size_t)(b*T_ + t0 + i0 + r)*H_ + h) << 6) + c0);
        *O4 = make_float4(p0.x, p0.y, p1.x, p1.y);
    }
}

// ===========================================================================
extern "C" void kernel_launch(void* const* d_in, const int* in_sizes, int n_in,
                              void* d_out, int out_size)
{
    const float* q       = (const float*)d_in[0];
    const float* k       = (const float*)d_in[1];
    const float* v       = (const float*)d_in[2];
    const float* graw    = (const float*)d_in[3];
    const float* beta    = (const float*)d_in[4];
    const float* A_log   = (const float*)d_in[5];
    const float* dt_bias = (const float*)d_in[6];
    float* out = (float*)d_out;

    cudaFuncSetAttribute(phase1_kernel,
        cudaFuncAttributeMaxDynamicSharedMemorySize, P1_BYTES);
    cudaFuncSetAttribute(phase3_kernel,
        cudaFuncAttributeMaxDynamicSharedMemorySize, P3_BYTES);

    phase1_kernel<<<NCHUNK, 256, P1_BYTES>>>(q, k, v, graw, beta, A_log, dt_bias);
    phase2_kernel<<<256, 32>>>();
    phase3_kernel<<<NCHUNK, 256, P3_BYTES>>>(out);
}

// round 9
// speedup vs baseline: 2.7335x; 1.2001x over previous
#include <cuda_runtime.h>
#include <cuda_bf16.h>
#include <math.h>

#define B_   2
#define T_   8192
#define H_   16
#define KD   32
#define VD   64
#define BT_  64
#define NT_  128
#define NCHUNK 4096   // B*H*NT

typedef unsigned long long ull;

__device__ __forceinline__ void fma2(ull& acc, ull a, ull b) {
    asm("fma.rn.f32x2 %0, %1, %2, %3;" : "=l"(acc) : "l"(a), "l"(b), "l"(acc));
}
__device__ __forceinline__ ull dup2(float x) {
    ull r; asm("mov.b64 %0, {%1, %2};" : "=l"(r) : "f"(x), "f"(x)); return r;
}
__device__ __forceinline__ float2 unpack2(ull v) {
    float2 r; asm("mov.b64 {%0, %1}, %2;" : "=f"(r.x), "=f"(r.y) : "l"(v)); return r;
}

// ---------------- tf32x3 mma helpers (m16n8k8) ----------------
__device__ __forceinline__ unsigned f2tf(float x) {
    unsigned r; asm("cvt.rna.tf32.f32 %0, %1;" : "=r"(r) : "f"(x)); return r;
}
__device__ __forceinline__ void split_tf(float x, unsigned& hi, unsigned& lo) {
    hi = f2tf(x);
    lo = f2tf(x - __uint_as_float(hi));
}
__device__ __forceinline__ void mma_m16n8k8(float c[4], const unsigned a[4], const unsigned b[2]) {
    asm volatile("mma.sync.aligned.m16n8k8.row.col.f32.tf32.tf32.f32 "
        "{%0,%1,%2,%3}, {%4,%5,%6,%7}, {%8,%9}, {%0,%1,%2,%3};"
        : "+f"(c[0]), "+f"(c[1]), "+f"(c[2]), "+f"(c[3])
        : "r"(a[0]), "r"(a[1]), "r"(a[2]), "r"(a[3]), "r"(b[0]), "r"(b[1]));
}
__device__ __forceinline__ void mma3(float c[4], const unsigned ahi[4], const unsigned alo[4],
                                     const unsigned bhi[2], const unsigned blo[2]) {
    mma_m16n8k8(c, ahi, bhi);
    mma_m16n8k8(c, ahi, blo);
    mma_m16n8k8(c, alo, bhi);
}
// A row-major fragment at (rows row,row+8; cols col,col+4)
__device__ __forceinline__ void loadA_frag(const float* A, int ld, int row, int col,
                                           unsigned hi[4], unsigned lo[4], float sgn) {
    float v0 = sgn * A[row*ld + col];
    float v1 = sgn * A[(row+8)*ld + col];
    float v2 = sgn * A[row*ld + col + 4];
    float v3 = sgn * A[(row+8)*ld + col + 4];
    split_tf(v0, hi[0], lo[0]); split_tf(v1, hi[1], lo[1]);
    split_tf(v2, hi[2], lo[2]); split_tf(v3, hi[3], lo[3]);
}
// B fragment from NT storage (B[n][k] row-major over n)
__device__ __forceinline__ void loadB_nt(const float* Bm, int ld, int nrow, int kcol,
                                         unsigned hi[2], unsigned lo[2]) {
    split_tf(Bm[nrow*ld + kcol],     hi[0], lo[0]);
    split_tf(Bm[nrow*ld + kcol + 4], hi[1], lo[1]);
}
// B fragment from KN storage (B[k][n] row-major over k)
__device__ __forceinline__ void loadB_kn(const float* Bm, int ld, int krow, int ncol,
                                         unsigned hi[2], unsigned lo[2]) {
    split_tf(Bm[krow*ld + ncol],       hi[0], lo[0]);
    split_tf(Bm[(krow+4)*ld + ncol],   hi[1], lo[1]);
}

// ------------------- device scratch (no allocation allowed) ---------------
__device__ float g_P [NCHUNK*KD*KD];
__device__ float g_C [NCHUNK*KD*VD];
__device__ float g_E [NCHUNK*KD];
__device__ float g_W [NCHUNK*BT_*KD];
__device__ float g_U [(size_t)NCHUNK*BT_*VD];
__device__ float g_QG[NCHUNK*BT_*KD];
__device__ float g_KD[NCHUNK*BT_*KD];           // kdR row-major [64][32]
__device__ float g_S [(size_t)NCHUNK*KD*VD];

// ---------------- phase-1 smem layout (floats) ----------------
#define P1_KQ   0        // b*kg [64][36]
#define P1_KD   2304     // kdR  [64][36]
#define P1_V    4608     // b*v [64][64]; gcum overlays [64][32]
#define P1_L    8704     // L [64][68]
#define P1_B    13056    // beta [64]
#define P1_E    13120    // e [32]
#define P1_BS   13152    // block sums [8][32]
#define P1_FLOATS 13408
#define P1_BYTES  (P1_FLOATS*4)      // 53632

// ---------------- phase-3 smem layout (floats) ----------------
#define P3_A    0        // Aqk [64][68]
#define P3_KD2  4352     // kdR [64][36]; later S [32][72]
#define P3_WQ   6656     // qg then w [64][36]
#define P3_VN   8960     // u -> v_new [64][72]
#define P3_FLOATS 13568
#define P3_BYTES  (P3_FLOATS*4)      // 54272

// ===========================================================================
__global__ void __launch_bounds__(256, 4) phase1_kernel(
    const float* __restrict__ q, const float* __restrict__ k,
    const float* __restrict__ v, const float* __restrict__ graw,
    const float* __restrict__ beta, const float* __restrict__ A_log,
    const float* __restrict__ dt_bias)
{
    extern __shared__ float sm[];
    float* sKQ = sm + P1_KQ;    // stride 36
    float* sKD = sm + P1_KD;    // stride 36
    float* sV  = sm + P1_V;     // stride 64
    float* sG  = sm + P1_V;     // overlay [64][32]
    float* sL  = sm + P1_L;     // stride 68
    float* sB  = sm + P1_B;
    float* sE  = sm + P1_E;
    float* sBS = sm + P1_BS;

    const int cid  = blockIdx.x;
    const int pair = cid >> 7, c = cid & 127;
    const int b    = pair >> 4, h = pair & 15;
    const int t0   = c * BT_;
    const int tid  = threadIdx.x;
    const int warp = tid >> 5, lane = tid & 31;
    const int gid  = lane >> 2, tg = lane & 3;
    const int m0   = (warp >> 1) << 4;
    const int n0   = (warp & 1) << 5;

    const float expA = __expf(A_log[h]);

    // ---- gate ----
    for (int idx = tid; idx < 512; idx += 256) {
        int i = idx >> 3, q4 = (idx & 7) << 2;
        float4 gr = *(const float4*)(graw + (((size_t)(b*T_ + t0 + i)*H_ + h) << 5) + q4);
        float4 db = *(const float4*)(dt_bias + h*KD + q4);
        float4 o;
        o.x = -expA*(fmaxf(gr.x+db.x,0.f) + log1pf(__expf(-fabsf(gr.x+db.x))));
        o.y = -expA*(fmaxf(gr.y+db.y,0.f) + log1pf(__expf(-fabsf(gr.y+db.y))));
        o.z = -expA*(fmaxf(gr.z+db.z,0.f) + log1pf(__expf(-fabsf(gr.z+db.z))));
        o.w = -expA*(fmaxf(gr.w+db.w,0.f) + log1pf(__expf(-fabsf(gr.w+db.w))));
        *(float4*)(sG + i*KD + q4) = o;
    }
    for (int i = tid; i < BT_; i += 256)
        sB[i] = beta[(size_t)(b*T_ + t0 + i)*H_ + h];
    __syncthreads();

    // ---- parallel cumsum ----
    {
        const int blk = tid >> 5, kk = tid & 31;
        float pref[8];
        float run = 0.f;
        #pragma unroll
        for (int t = 0; t < 8; t++) {
            run += sG[(blk*8 + t)*KD + kk];
            pref[t] = run;
        }
        sBS[blk*32 + kk] = run;
        __syncthreads();
        float pre = 0.f;
        #pragma unroll
        for (int j = 0; j < 7; j++)
            if (j < blk) pre += sBS[j*32 + kk];
        #pragma unroll
        for (int t = 0; t < 8; t++)
            sG[(blk*8 + t)*KD + kk] = fmaxf(pre + pref[t], -80.f);
        if (blk == 7) sE[kk] = __expf(fmaxf(pre + pref[7], -80.f));
    }
    __syncthreads();

    // ---- k,q rows: b*kg -> sKQ, kdR -> sKD, qg -> g_QG ----
    for (int r = warp; r < BT_; r += 8) {
        float gc = sG[r*KD + lane];
        float eg = __expf(gc);

        float kv = k[((size_t)((b*T_+t0+r)*H_ + h) << 5) + lane];
        float ss = kv*kv;
        #pragma unroll
        for (int o = 16; o; o >>= 1) ss += __shfl_xor_sync(0xffffffffu, ss, o);
        float kn = kv / fmaxf(sqrtf(ss), 1e-6f);
        sKQ[r*36 + lane] = sB[r] * kn * eg;
        sKD[r*36 + lane] = kn * __expf(-gc);

        float qv = q[((size_t)((b*T_+t0+r)*H_+h) << 5) + lane];
        float qs = qv*qv;
        #pragma unroll
        for (int o = 16; o; o >>= 1) qs += __shfl_xor_sync(0xffffffffu, qs, o);
        float qn = 0.1767766952966369f * qv / fmaxf(sqrtf(qs), 1e-6f);
        g_QG[(size_t)cid*2048 + r*KD + lane] = qn * eg;
    }
    __syncthreads();   // sG dead

    // ---- b*v -> sV ----
    for (int idx = tid; idx < 1024; idx += 256) {
        int i = idx >> 4, c4 = (idx & 15) << 2;
        float4 vv = *(const float4*)(v + (((size_t)(b*T_+t0+i)*H_+h) << 6) + c4);
        float bi = sB[i];
        vv.x *= bi; vv.y *= bi; vv.z *= bi; vv.w *= bi;
        *(float4*)(sV + i*64 + c4) = vv;
    }

    // ---- L = (b*kg) @ kdR^T via tf32x3 mma ----
    {
        float lac[4][4];
        #pragma unroll
        for (int nt = 0; nt < 4; nt++)
            #pragma unroll
            for (int r = 0; r < 4; r++) lac[nt][r] = 0.f;
        #pragma unroll
        for (int kt = 0; kt < 4; kt++) {
            const int k0 = kt << 3;
            unsigned ahi[4], alo[4];
            loadA_frag(sKQ, 36, m0 + gid, k0 + tg, ahi, alo, 1.f);
            #pragma unroll
            for (int nt = 0; nt < 4; nt++) {
                unsigned bhi[2], blo[2];
                loadB_nt(sKD, 36, n0 + nt*8 + gid, k0 + tg, bhi, blo);
                mma3(lac[nt], ahi, alo, bhi, blo);
            }
        }
        #pragma unroll
        for (int nt = 0; nt < 4; nt++) {
            const int cb = n0 + nt*8 + 2*tg;
            sL[(m0+gid)*68 + cb]     = lac[nt][0];
            sL[(m0+gid)*68 + cb + 1] = lac[nt][1];
            sL[(m0+gid+8)*68 + cb]     = lac[nt][2];
            sL[(m0+gid+8)*68 + cb + 1] = lac[nt][3];
        }
    }
    __syncthreads();

    // ---- blocked forward substitution on x = [sKQ(36) | sV(64)] ----
    #pragma unroll 1
    for (int blk = 0; blk < 4; ++blk) {
        const int r0 = blk << 4;
        if (blk) {
            if (tid < 96) {
                const int rg = tid & 3, cgs = tid >> 2;
                float* xb; int strd, xc;
                if (cgs < 8) { xb = sKQ; strd = 36; xc = cgs << 2; }
                else         { xb = sV;  strd = 64; xc = (cgs - 8) << 2; }
                const int rb = r0 + (rg << 2);
                ull acc[8];
                #pragma unroll
                for (int r = 0; r < 4; r++) {
                    ulonglong2 u2 = *(const ulonglong2*)(xb + (rb+r)*strd + xc);
                    acc[r*2] = u2.x; acc[r*2+1] = u2.y;
                }
                #pragma unroll 1
                for (int kx = 0; kx < r0; kx += 4) {
                    float Lv[4][4];
                    #pragma unroll
                    for (int r = 0; r < 4; r++)
                        *(float4*)Lv[r] = *(const float4*)(sL + (rb+r)*68 + kx);
                    #pragma unroll
                    for (int t = 0; t < 4; t++) {
                        ulonglong2 bv = *(const ulonglong2*)(xb + (kx+t)*strd + xc);
                        #pragma unroll
                        for (int r = 0; r < 4; r++) {
                            ull a = dup2(-Lv[r][t]);
                            fma2(acc[r*2], a, bv.x); fma2(acc[r*2+1], a, bv.y);
                        }
                    }
                }
                #pragma unroll
                for (int r = 0; r < 4; r++) {
                    ulonglong2 u2; u2.x = acc[r*2]; u2.y = acc[r*2+1];
                    *(ulonglong2*)(xb + (rb+r)*strd + xc) = u2;
                }
            }
            __syncthreads();
        }
        if (tid < 96) {
            float xr[16];
            if (tid < 32) {
                #pragma unroll
                for (int i = 0; i < 16; i++) xr[i] = sKQ[(r0+i)*36 + tid];
            } else {
                const int cc = tid - 32;
                #pragma unroll
                for (int i = 0; i < 16; i++) xr[i] = sV[(r0+i)*64 + cc];
            }
            #pragma unroll
            for (int i = 1; i < 16; i++) {
                const float* Lr = sL + (r0+i)*68 + r0;
                #pragma unroll
                for (int j = 0; j < i; j++)
                    xr[i] = fmaf(-Lr[j], xr[j], xr[i]);
            }
            if (tid < 32) {
                #pragma unroll
                for (int i = 1; i < 16; i++) sKQ[(r0+i)*36 + tid] = xr[i];
            } else {
                const int cc = tid - 32;
                #pragma unroll
                for (int i = 1; i < 16; i++) sV[(r0+i)*64 + cc] = xr[i];
            }
        }
        __syncthreads();
    }
    // w in sKQ, u in sV

    // ---- fused P|C = e * (kdR^T @ [w|u]) ----
    if (tid < 192) {
        const int kkg = tid & 7, cg = tid >> 3;
        const int kk0 = kkg << 2;
        float* xb; int strd, xc;
        if (cg < 8) { xb = sKQ; strd = 36; xc = cg << 2; }
        else        { xb = sV;  strd = 64; xc = (cg - 8) << 2; }
        ull acc[8];
        #pragma unroll
        for (int r = 0; r < 8; r++) acc[r] = 0ull;
        #pragma unroll 4
        for (int i = 0; i < BT_; i++) {
            float a4[4];
            *(float4*)a4 = *(const float4*)(sKD + i*36 + kk0);
            ulonglong2 bv = *(const ulonglong2*)(xb + i*strd + xc);
            #pragma unroll
            for (int r = 0; r < 4; r++) {
                ull ad = dup2(a4[r]);
                fma2(acc[r*2], ad, bv.x); fma2(acc[r*2+1], ad, bv.y);
            }
        }
        #pragma unroll
        for (int r = 0; r < 4; r++) {
            float e = sE[kk0 + r];
            float2 p0 = unpack2(acc[r*2]), p1 = unpack2(acc[r*2+1]);
            float4 val = make_float4(e*p0.x, e*p0.y, e*p1.x, e*p1.y);
            if (cg < 8)
                *(float4*)(g_P + (size_t)cid*1024 + (kk0+r)*32 + (cg<<2)) = val;
            else
                *(float4*)(g_C + (size_t)cid*2048 + (kk0+r)*64 + ((cg-8)<<2)) = val;
        }
    }
    if (tid < KD) g_E[cid*KD + tid] = sE[tid];

    // ---- store w, u, kdR ----
    for (int idx = tid; idx < 512; idx += 256) {
        int i = idx >> 3, c4 = (idx & 7) << 2;
        *(float4*)(g_W + (size_t)cid*2048 + i*32 + c4) =
            *(const float4*)(sKQ + i*36 + c4);
    }
    for (int idx = tid; idx < 1024; idx += 256) {
        int i = idx >> 4, c4 = (idx & 15) << 2;
        *(float4*)(g_U + (size_t)cid*4096 + i*64 + c4) =
            *(const float4*)(sV + i*64 + c4);
    }
    for (int idx = tid; idx < 512; idx += 256) {
        int i = idx >> 3, c4 = (idx & 7) << 2;
        *(float4*)(g_KD + (size_t)cid*2048 + i*32 + c4) =
            *(const float4*)(sKD + i*36 + c4);
    }
}

// ===========================================================================
// Phase 2: S_{t+1} = diag(e)S - P S + C.  1 warp per (pair, 8-col slice).
// ===========================================================================
#define P4C(arr, m) ( ((m)&3)==0 ? arr[(m)>>2].x : ((m)&3)==1 ? arr[(m)>>2].y \
                    : ((m)&3)==2 ? arr[(m)>>2].z : arr[(m)>>2].w )

__global__ void __launch_bounds__(32) phase2_kernel()
{
    const int p     = blockIdx.x >> 3;
    const int vbase = (blockIdx.x & 7) << 3;
    const int lane  = threadIdx.x;
    const size_t base = (size_t)p*128;

    float4 Pc[8], Pn[8], Cc[2], Cn[2];
    float  ec, en;
    float  s[8];
    #pragma unroll
    for (int j = 0; j < 8; j++) s[j] = 0.f;

    {
        const float4* Pp = (const float4*)(g_P + base*1024 + lane*32);
        #pragma unroll
        for (int r = 0; r < 8; r++) Pc[r] = Pp[r];
        const float4* Cp = (const float4*)(g_C + base*2048 + lane*64 + vbase);
        Cc[0] = Cp[0]; Cc[1] = Cp[1];
        ec = g_E[base*32 + lane];
    }

    #pragma unroll 1
    for (int t = 0; t < 128; t++) {
        const size_t cid = base + t;
        if (t + 1 < 128) {
            const size_t cid1 = cid + 1;
            const float4* Pp = (const float4*)(g_P + cid1*1024 + lane*32);
            #pragma unroll
            for (int r = 0; r < 8; r++) Pn[r] = Pp[r];
            const float4* Cp = (const float4*)(g_C + cid1*2048 + lane*64 + vbase);
            Cn[0] = Cp[0]; Cn[1] = Cp[1];
            en = g_E[cid1*32 + lane];
        }
        float4* Sp = (float4*)(g_S + cid*2048 + lane*64 + vbase);
        Sp[0] = make_float4(s[0], s[1], s[2], s[3]);
        Sp[1] = make_float4(s[4], s[5], s[6], s[7]);

        float acc[8];
        acc[0]=fmaf(ec,s[0],Cc[0].x); acc[1]=fmaf(ec,s[1],Cc[0].y);
        acc[2]=fmaf(ec,s[2],Cc[0].z); acc[3]=fmaf(ec,s[3],Cc[0].w);
        acc[4]=fmaf(ec,s[4],Cc[1].x); acc[5]=fmaf(ec,s[5],Cc[1].y);
        acc[6]=fmaf(ec,s[6],Cc[1].z); acc[7]=fmaf(ec,s[7],Cc[1].w);

        #pragma unroll
        for (int m = 0; m < 32; m++) {
            float pm = P4C(Pc, m);
            #pragma unroll
            for (int j = 0; j < 8; j++)
                acc[j] = fmaf(-pm, __shfl_sync(0xffffffffu, s[j], m), acc[j]);
        }
        #pragma unroll
        for (int j = 0; j < 8; j++) s[j] = acc[j];
        #pragma unroll
        for (int r = 0; r < 8; r++) Pc[r] = Pn[r];
        Cc[0] = Cn[0]; Cc[1] = Cn[1];
        ec = en;
    }
}

// ===========================================================================
// Phase 3: o = qg S + Aqk (u - w S) — all GEMMs via tf32x3 mma
// ===========================================================================
__global__ void __launch_bounds__(256, 4) phase3_kernel(float* __restrict__ out)
{
    extern __shared__ float sm[];
    float* sA  = sm + P3_A;     // Aqk [64][68]
    float* sKD = sm + P3_KD2;   // kdR [64][36]
    float* sS  = sm + P3_KD2;   // S [32][72] (overlays kdR after GEMM1)
    float* sWQ = sm + P3_WQ;    // qg then w [64][36]
    float* sVn = sm + P3_VN;    // u -> v_new [64][72]

    const int cid  = blockIdx.x;
    const int pair = cid >> 7, c = cid & 127;
    const int b    = pair >> 4, h = pair & 15;
    const int t0   = c * BT_;
    const int tid  = threadIdx.x;
    const int warp = tid >> 5, lane = tid & 31;
    const int gid  = lane >> 2, tg = lane & 3;
    const int m0   = (warp >> 1) << 4;
    const int n0   = (warp & 1) << 5;

    // ---- load qg, kdR, u ----
    for (int idx = tid; idx < 512; idx += 256) {
        int i = idx >> 3, c4 = (idx & 7) << 2;
        *(float4*)(sWQ + i*36 + c4) =
            *(const float4*)(g_QG + (size_t)cid*2048 + i*32 + c4);
    }
    for (int idx = tid; idx < 512; idx += 256) {
        int i = idx >> 3, c4 = (idx & 7) << 2;
        *(float4*)(sKD + i*36 + c4) =
            *(const float4*)(g_KD + (size_t)cid*2048 + i*32 + c4);
    }
    for (int idx = tid; idx < 1024; idx += 256) {
        int i = idx >> 4, c4 = (idx & 15) << 2;
        *(float4*)(sVn + i*72 + c4) =
            *(const float4*)(g_U + (size_t)cid*4096 + i*64 + c4);
    }
    __syncthreads();

    // ---- GEMM1: Aqk = qg @ kdR^T -> sA ----
    {
        float aq[4][4];
        #pragma unroll
        for (int nt = 0; nt < 4; nt++)
            #pragma unroll
            for (int r = 0; r < 4; r++) aq[nt][r] = 0.f;
        #pragma unroll
        for (int kt = 0; kt < 4; kt++) {
            const int k0 = kt << 3;
            unsigned ahi[4], alo[4];
            loadA_frag(sWQ, 36, m0 + gid, k0 + tg, ahi, alo, 1.f);
            #pragma unroll
            for (int nt = 0; nt < 4; nt++) {
                unsigned bhi[2], blo[2];
                loadB_nt(sKD, 36, n0 + nt*8 + gid, k0 + tg, bhi, blo);
                mma3(aq[nt], ahi, alo, bhi, blo);
            }
        }
        #pragma unroll
        for (int nt = 0; nt < 4; nt++) {
            const int cb = n0 + nt*8 + 2*tg;
            sA[(m0+gid)*68 + cb]       = aq[nt][0];
            sA[(m0+gid)*68 + cb + 1]   = aq[nt][1];
            sA[(m0+gid+8)*68 + cb]     = aq[nt][2];
            sA[(m0+gid+8)*68 + cb + 1] = aq[nt][3];
        }
    }
    __syncthreads();   // kdR dead; Aqk visible

    // ---- load S over kdR region [32][72] ----
    for (int idx = tid; idx < 512; idx += 256) {
        int kk = idx >> 4, c4 = (idx & 15) << 2;
        *(float4*)(sS + kk*72 + c4) =
            *(const float4*)(g_S + (size_t)cid*2048 + kk*64 + c4);
    }
    __syncthreads();

    // ---- GEMM2: oacc = qg @ S ----
    float oac[4][4];
    #pragma unroll
    for (int nt = 0; nt < 4; nt++)
        #pragma unroll
        for (int r = 0; r < 4; r++) oac[nt][r] = 0.f;
    #pragma unroll
    for (int kt = 0; kt < 4; kt++) {
        const int k0 = kt << 3;
        unsigned ahi[4], alo[4];
        loadA_frag(sWQ, 36, m0 + gid, k0 + tg, ahi, alo, 1.f);
        #pragma unroll
        for (int nt = 0; nt < 4; nt++) {
            unsigned bhi[2], blo[2];
            loadB_kn(sS, 72, k0 + tg, n0 + nt*8 + gid, bhi, blo);
            mma3(oac[nt], ahi, alo, bhi, blo);
        }
    }
    __syncthreads();   // qg dead

    // ---- load w over qg ----
    for (int idx = tid; idx < 512; idx += 256) {
        int i = idx >> 3, c4 = (idx & 7) << 2;
        *(float4*)(sWQ + i*36 + c4) =
            *(const float4*)(g_W + (size_t)cid*2048 + i*32 + c4);
    }
    __syncthreads();

    // ---- GEMM3: v_new = u + (-w) @ S, RMW into sVn ----
    {
        float ws[4][4];
        #pragma unroll
        for (int nt = 0; nt < 4; nt++)
            #pragma unroll
            for (int r = 0; r < 4; r++) ws[nt][r] = 0.f;
        #pragma unroll
        for (int kt = 0; kt < 4; kt++) {
            const int k0 = kt << 3;
            unsigned ahi[4], alo[4];
            loadA_frag(sWQ, 36, m0 + gid, k0 + tg, ahi, alo, -1.f);
            #pragma unroll
            for (int nt = 0; nt < 4; nt++) {
                unsigned bhi[2], blo[2];
                loadB_kn(sS, 72, k0 + tg, n0 + nt*8 + gid, bhi, blo);
                mma3(ws[nt], ahi, alo, bhi, blo);
            }
        }
        #pragma unroll
        for (int nt = 0; nt < 4; nt++) {
            const int cb = n0 + nt*8 + 2*tg;
            sVn[(m0+gid)*72 + cb]       += ws[nt][0];
            sVn[(m0+gid)*72 + cb + 1]   += ws[nt][1];
            sVn[(m0+gid+8)*72 + cb]     += ws[nt][2];
            sVn[(m0+gid+8)*72 + cb + 1] += ws[nt][3];
        }
    }
    __syncthreads();

    // ---- GEMM5: oacc += tril(Aqk) @ v_new ----
    {
        const int ktmax = (m0 + 15) >> 3;   // 1,3,5,7 per warpM
        #pragma unroll 2
        for (int kt = 0; kt <= ktmax; kt++) {
            const int k0 = kt << 3;
            const int r0i = m0 + gid, r1i = m0 + gid + 8;
            float v0 = (k0 + tg     <= r0i) ? sA[r0i*68 + k0 + tg]     : 0.f;
            float v1 = (k0 + tg     <= r1i) ? sA[r1i*68 + k0 + tg]     : 0.f;
            float v2 = (k0 + tg + 4 <= r0i) ? sA[r0i*68 + k0 + tg + 4] : 0.f;
            float v3 = (k0 + tg + 4 <= r1i) ? sA[r1i*68 + k0 + tg + 4] : 0.f;
            unsigned ahi[4], alo[4];
            split_tf(v0, ahi[0], alo[0]); split_tf(v1, ahi[1], alo[1]);
            split_tf(v2, ahi[2], alo[2]); split_tf(v3, ahi[3], alo[3]);
            #pragma unroll
            for (int nt = 0; nt < 4; nt++) {
                unsigned bhi[2], blo[2];
                loadB_kn(sVn, 72, k0 + tg, n0 + nt*8 + gid, bhi, blo);
                mma3(oac[nt], ahi, alo, bhi, blo);
            }
        }
    }

    // ---- store out from c-fragments ----
    #pragma unroll
    for (int nt = 0; nt < 4; nt++) {
        const int cb = n0 + nt*8 + 2*tg;
        const size_t r0o = (((size_t)(b*T_ + t0 + m0 + gid)*H_ + h) << 6);
        const size_t r1o = (((size_t)(b*T_ + t0 + m0 + gid + 8)*H_ + h) << 6);
        out[r0o + cb]     = oac[nt][0];
        out[r0o + cb + 1] = oac[nt][1];
        out[r1o + cb]     = oac[nt][2];
        out[r1o + cb + 1] = oac[nt][3];
    }
}

// ===========================================================================
extern "C" void kernel_launch(void* const* d_in, const int* in_sizes, int n_in,
                              void* d_out, int out_size)
{
    const float* q       = (const float*)d_in[0];
    const float* k       = (const float*)d_in[1];
    const float* v       = (const float*)d_in[2];
    const float* graw    = (const float*)d_in[3];
    const float* beta    = (const float*)d_in[4];
    const float* A_log   = (const float*)d_in[5];
    const float* dt_bias = (const float*)d_in[6];
    float* out = (float*)d_out;

    cudaFuncSetAttribute(phase1_kernel,
        cudaFuncAttributeMaxDynamicSharedMemorySize, P1_BYTES);
    cudaFuncSetAttribute(phase3_kernel,
        cudaFuncAttributeMaxDynamicSharedMemorySize, P3_BYTES);

    phase1_kernel<<<NCHUNK, 256, P1_BYTES>>>(q, k, v, graw, beta, A_log, dt_bias);
    phase2_kernel<<<256, 32>>>();
    phase3_kernel<<<NCHUNK, 256, P3_BYTES>>>(out);
}